// round 1
// baseline (speedup 1.0000x reference)
#include <cuda_runtime.h>
#include <cuda_bf16.h>
#include <math.h>

// Problem shape (fixed by setup_inputs)
constexpr int Bc  = 2;
constexpr int Sc  = 2048;
constexpr int Dc  = 1024;
constexpr int Hc  = 8;
constexpr int HDc = 128;

// Scratch (no allocations allowed): 16 + 32 + 32 MB + tiny
__device__ float g_inv_dsq[(size_t)Sc * Sc];    // 1 / (warped dist^2 + eps)
__device__ float g_masses[Bc * Hc * Sc];        // sigmoid(x . mass_w), [bh][s]
__device__ float g_v[(size_t)Bc * Sc * Dc];     // x @ v_w^T
__device__ float g_ho[(size_t)Bc * Sc * Dc];    // head_out, [b][q][h*HD+d]

// ---------------------------------------------------------------------------
// 1) inv_dsq[q][k] = 1 / (d'(q,k)^2 + 1e-6),  d' = d*(1+0.15*sin(d)), d = |p_q-p_k|
// ---------------------------------------------------------------------------
__global__ void dist_kernel(const float* __restrict__ pos) {
    int q = blockIdx.y;
    int k = blockIdx.x * blockDim.x + threadIdx.x;
    float acc = 1e-12f;
#pragma unroll
    for (int j = 0; j < 8; j++) {
        float d = pos[q * 8 + j] - pos[k * 8 + j];
        acc = fmaf(d, d, acc);
    }
    float dist = sqrtf(acc);
    dist = dist * (1.0f + 0.15f * sinf(dist));
    dist = fmaxf(dist, 0.0f);
    float dsq = fmaf(dist, dist, 1e-6f);
    g_inv_dsq[(size_t)q * Sc + k] = 1.0f / dsq;
}

// ---------------------------------------------------------------------------
// 2) masses[bh][s] = sigmoid( sum_d x[b,s,h*128+d] * mass_w[h,d] )
//    One warp per (b,h,s).
// ---------------------------------------------------------------------------
__global__ __launch_bounds__(256) void masses_kernel(const float* __restrict__ x,
                                                     const float* __restrict__ mw) {
    int gw   = blockIdx.x * 8 + (threadIdx.x >> 5);
    int lane = threadIdx.x & 31;
    int bh = gw / Sc;
    int s  = gw % Sc;
    int b = bh >> 3, h = bh & 7;
    const float4* xp = (const float4*)(x + ((size_t)(b * Sc + s)) * Dc + h * HDc);
    const float4* wp = (const float4*)(mw + h * HDc);
    float4 a = xp[lane];
    float4 w = wp[lane];
    float dot = a.x * w.x + a.y * w.y + a.z * w.z + a.w * w.w;
#pragma unroll
    for (int o = 16; o; o >>= 1) dot += __shfl_xor_sync(0xffffffffu, dot, o);
    if (lane == 0) g_masses[bh * Sc + s] = 1.0f / (1.0f + __expf(-dot));
}

// ---------------------------------------------------------------------------
// 3/5) SGEMM  C[M,N] = A[M,K] * B[N,K]^T   (both row-major, K-contiguous)
//      128x128 tile, BK=16, 256 threads, 8x8 per thread.
// ---------------------------------------------------------------------------
__global__ __launch_bounds__(256) void sgemm_nt(const float* __restrict__ A,
                                                const float* __restrict__ Bm,
                                                float* __restrict__ C,
                                                int M, int N, int K) {
    constexpr int BM = 128, BN = 128, BK = 16;
    __shared__ float As[BK][BM + 4];
    __shared__ float Bs[BK][BN + 4];
    int tid  = threadIdx.x;
    int row0 = blockIdx.y * BM;
    int col0 = blockIdx.x * BN;
    int tm = (tid >> 4) * 8;
    int tn = (tid & 15) * 8;
    float acc[8][8] = {};
    for (int k0 = 0; k0 < K; k0 += BK) {
#pragma unroll
        for (int i = 0; i < 2; i++) {
            int idx = tid + i * 256;          // 0..511 float4 slots
            int r   = idx >> 2;
            int c4  = (idx & 3) * 4;
            float4 a = *(const float4*)&A[(size_t)(row0 + r) * K + k0 + c4];
            As[c4 + 0][r] = a.x; As[c4 + 1][r] = a.y;
            As[c4 + 2][r] = a.z; As[c4 + 3][r] = a.w;
            float4 b = *(const float4*)&Bm[(size_t)(col0 + r) * K + k0 + c4];
            Bs[c4 + 0][r] = b.x; Bs[c4 + 1][r] = b.y;
            Bs[c4 + 2][r] = b.z; Bs[c4 + 3][r] = b.w;
        }
        __syncthreads();
#pragma unroll
        for (int kk = 0; kk < BK; kk++) {
            float ar[8], br[8];
            *(float4*)&ar[0] = *(float4*)&As[kk][tm];
            *(float4*)&ar[4] = *(float4*)&As[kk][tm + 4];
            *(float4*)&br[0] = *(float4*)&Bs[kk][tn];
            *(float4*)&br[4] = *(float4*)&Bs[kk][tn + 4];
#pragma unroll
            for (int i = 0; i < 8; i++)
#pragma unroll
                for (int j = 0; j < 8; j++)
                    acc[i][j] = fmaf(ar[i], br[j], acc[i][j]);
        }
        __syncthreads();
    }
#pragma unroll
    for (int i = 0; i < 8; i++) {
        float4 o0 = make_float4(acc[i][0], acc[i][1], acc[i][2], acc[i][3]);
        float4 o1 = make_float4(acc[i][4], acc[i][5], acc[i][6], acc[i][7]);
        *(float4*)&C[(size_t)(row0 + tm + i) * N + col0 + tn]     = o0;
        *(float4*)&C[(size_t)(row0 + tm + i) * N + col0 + tn + 4] = o1;
    }
}

// ---------------------------------------------------------------------------
// 4) Fused attention (no max subtraction needed: force in (0,50])
//    Block: 128 threads, q-tile 64, k-tile 32, full hd=128.
//    ho[b,q,h,:] = (sum_k w * v[b,k,h,:]) / (sum_k w),
//    w = exp(min(mq*mk*inv_dsq, 50))
// ---------------------------------------------------------------------------
constexpr int AQ = 64;
constexpr int AK = 32;

__global__ __launch_bounds__(128) void attn_kernel() {
    __shared__ float vs[AK][HDc];     // 16 KB, [k][d]
    __shared__ float ws[AK][AQ];      //  8 KB, [k][q]  (transposed for f4 reads)
    __shared__ float s_mq[AQ];
    __shared__ float s_sum[AQ];
    __shared__ float s_part[128];

    int tid = threadIdx.x;
    int bh  = blockIdx.y;
    int b = bh >> 3, h = bh & 7;
    int q0 = blockIdx.x * AQ;

    if (tid < AQ) {
        s_mq[tid]  = g_masses[bh * Sc + q0 + tid];
        s_sum[tid] = 0.0f;
    }
    int tq  = tid >> 4;             // 0..7   (q octet)
    int tn  = (tid & 15) * 8;       // d offset
    int myq = tid & 63;             // q row handled in score phase
    int kh  = (tid >> 6) * 16;      // k half (0 or 16)

    const float* vbase = g_v + (size_t)b * Sc * Dc + (size_t)h * HDc;
    const float* mrow  = g_masses + bh * Sc;
    const float* drow  = g_inv_dsq + (size_t)(q0 + myq) * Sc;

    float acc[8][8] = {};
    __syncthreads();

    for (int k0 = 0; k0 < Sc; k0 += AK) {
        // load v tile: AK*HD = 4096 floats = 1024 f4 / 128 thr
#pragma unroll
        for (int i = 0; i < 8; i++) {
            int idx = tid + i * 128;
            int r   = idx >> 5;
            int c   = (idx & 31) * 4;
            *(float4*)&vs[r][c] = *(const float4*)&vbase[(size_t)(k0 + r) * Dc + c];
        }
        // scores: 16 per thread (one q row, half a k tile)
        float mq = s_mq[myq];
        float lsum = 0.0f;
#pragma unroll
        for (int j = 0; j < 16; j += 4) {
            float4 iv = *(const float4*)&drow[k0 + kh + j];
            float4 mk = *(const float4*)&mrow[k0 + kh + j];
            float w0 = __expf(fminf(mq * mk.x * iv.x, 50.0f));
            float w1 = __expf(fminf(mq * mk.y * iv.y, 50.0f));
            float w2 = __expf(fminf(mq * mk.z * iv.z, 50.0f));
            float w3 = __expf(fminf(mq * mk.w * iv.w, 50.0f));
            ws[kh + j + 0][myq] = w0;
            ws[kh + j + 1][myq] = w1;
            ws[kh + j + 2][myq] = w2;
            ws[kh + j + 3][myq] = w3;
            lsum += (w0 + w1) + (w2 + w3);
        }
        s_part[tid] = lsum;
        __syncthreads();
        if (tid < AQ) s_sum[tid] += s_part[tid] + s_part[tid + AQ];
        // P @ V
#pragma unroll 4
        for (int kk = 0; kk < AK; kk++) {
            float wr[8], vr[8];
            *(float4*)&wr[0] = *(float4*)&ws[kk][tq * 8];
            *(float4*)&wr[4] = *(float4*)&ws[kk][tq * 8 + 4];
            *(float4*)&vr[0] = *(float4*)&vs[kk][tn];
            *(float4*)&vr[4] = *(float4*)&vs[kk][tn + 4];
#pragma unroll
            for (int i = 0; i < 8; i++)
#pragma unroll
                for (int j = 0; j < 8; j++)
                    acc[i][j] = fmaf(wr[i], vr[j], acc[i][j]);
        }
        __syncthreads();
    }

    // normalize + write head_out
    float* obase = g_ho + ((size_t)(b * Sc + q0)) * Dc + (size_t)h * HDc;
#pragma unroll
    for (int i = 0; i < 8; i++) {
        int q = tq * 8 + i;
        float r = 1.0f / s_sum[q];
        float4 o0 = make_float4(acc[i][0] * r, acc[i][1] * r, acc[i][2] * r, acc[i][3] * r);
        float4 o1 = make_float4(acc[i][4] * r, acc[i][5] * r, acc[i][6] * r, acc[i][7] * r);
        *(float4*)&obase[(size_t)q * Dc + tn]     = o0;
        *(float4*)&obase[(size_t)q * Dc + tn + 4] = o1;
    }
}

// ---------------------------------------------------------------------------
extern "C" void kernel_launch(void* const* d_in, const int* in_sizes, int n_in,
                              void* d_out, int out_size) {
    const float* x      = (const float*)d_in[0];
    const float* mass_w = (const float*)d_in[1];
    const float* v_w    = (const float*)d_in[2];
    const float* out_w  = (const float*)d_in[3];
    const float* pos    = (const float*)d_in[4];
    float* out = (float*)d_out;

    void* pv  = nullptr;
    void* pho = nullptr;
    cudaGetSymbolAddress(&pv,  g_v);
    cudaGetSymbolAddress(&pho, g_ho);

    // 1) geometry
    dist_kernel<<<dim3(Sc / 256, Sc), 256>>>(pos);
    // 2) masses
    masses_kernel<<<(Bc * Hc * Sc) / 8, 256>>>(x, mass_w);
    // 3) v = x @ v_w^T
    sgemm_nt<<<dim3(Dc / 128, (Bc * Sc) / 128), 256>>>(x, v_w, (float*)pv,
                                                       Bc * Sc, Dc, Dc);
    // 4) fused attention -> head_out
    attn_kernel<<<dim3(Sc / AQ, Bc * Hc), 128>>>();
    // 5) out = head_out @ out_w^T
    sgemm_nt<<<dim3(Dc / 128, (Bc * Sc) / 128), 256>>>((const float*)pho, out_w, out,
                                                       Bc * Sc, Dc, Dc);
}

// round 3
// speedup vs baseline: 2.3038x; 2.3038x over previous
#include <cuda_runtime.h>
#include <cstdint>
#include <math.h>

// Problem shape (fixed by setup_inputs)
constexpr int Bc  = 2;
constexpr int Sc  = 2048;
constexpr int Dc  = 1024;
constexpr int Hc  = 8;
constexpr int HDc = 128;

// Scratch (no allocations allowed)
__device__ float g_inv_dsq[(size_t)Sc * Sc];          // 16 MB
__device__ float g_masses[Bc * Hc * Sc];              // 128 KB
__device__ float g_v[(size_t)Bc * Sc * Dc];           // 32 MB
__device__ float g_vT[(size_t)Bc * Hc * HDc * Sc];    // 32 MB  [bh][d][k]
__device__ float g_ho[(size_t)Bc * Sc * Dc];          // 32 MB

// ---------------------------------------------------------------------------
// tf32 helpers (plain sm_100-safe: mma.sync has existed since sm_80)
// ---------------------------------------------------------------------------
__device__ __forceinline__ uint32_t cvt_tf32(float x) {
    uint32_t r;
    asm("cvt.rna.tf32.f32 %0, %1;" : "=r"(r) : "f"(x));
    return r;
}

__device__ __forceinline__ void mma_m16n8k8(float c[4], const uint32_t a[4],
                                            const uint32_t b[2]) {
    asm volatile(
        "mma.sync.aligned.m16n8k8.row.col.f32.tf32.tf32.f32 "
        "{%0,%1,%2,%3}, {%4,%5,%6,%7}, {%8,%9}, {%0,%1,%2,%3};"
        : "+f"(c[0]), "+f"(c[1]), "+f"(c[2]), "+f"(c[3])
        : "r"(a[0]), "r"(a[1]), "r"(a[2]), "r"(a[3]), "r"(b[0]), "r"(b[1]));
}

// ---------------------------------------------------------------------------
// 1) inv_dsq[q][k] = 1 / (d'(q,k)^2 + 1e-6)
// ---------------------------------------------------------------------------
__global__ void dist_kernel(const float* __restrict__ pos) {
    int q = blockIdx.y;
    int k = blockIdx.x * blockDim.x + threadIdx.x;
    float acc = 1e-12f;
#pragma unroll
    for (int j = 0; j < 8; j++) {
        float d = pos[q * 8 + j] - pos[k * 8 + j];
        acc = fmaf(d, d, acc);
    }
    float dist = sqrtf(acc);
    dist = dist * (1.0f + 0.15f * sinf(dist));
    dist = fmaxf(dist, 0.0f);
    float dsq = fmaf(dist, dist, 1e-6f);
    g_inv_dsq[(size_t)q * Sc + k] = 1.0f / dsq;
}

// ---------------------------------------------------------------------------
// 2) masses[bh][s] = sigmoid( x[b,s,h*128:] . mass_w[h,:] )
// ---------------------------------------------------------------------------
__global__ __launch_bounds__(256) void masses_kernel(const float* __restrict__ x,
                                                     const float* __restrict__ mw) {
    int gw   = blockIdx.x * 8 + (threadIdx.x >> 5);
    int lane = threadIdx.x & 31;
    int bh = gw / Sc;
    int s  = gw % Sc;
    int b = bh >> 3, h = bh & 7;
    const float4* xp = (const float4*)(x + ((size_t)(b * Sc + s)) * Dc + h * HDc);
    const float4* wp = (const float4*)(mw + h * HDc);
    float4 a = xp[lane];
    float4 w = wp[lane];
    float dot = a.x * w.x + a.y * w.y + a.z * w.z + a.w * w.w;
#pragma unroll
    for (int o = 16; o; o >>= 1) dot += __shfl_xor_sync(0xffffffffu, dot, o);
    if (lane == 0) g_masses[bh * Sc + s] = 1.0f / (1.0f + __expf(-dot));
}

// ---------------------------------------------------------------------------
// 3/6) tf32 mma.sync GEMM: C[M,N] = A[M,K] * B[N,K]^T  (row-major, K contig)
//      128x128 tile, BK=32, 256 threads (8 warps 4x2), warp does 32x64.
// ---------------------------------------------------------------------------
__global__ __launch_bounds__(256) void gemm_tf32(const float* __restrict__ A,
                                                 const float* __restrict__ B,
                                                 float* __restrict__ C,
                                                 int N, int K) {
    __shared__ uint32_t As[128][36];   // [m][k], stride 36 -> conflict-free frags
    __shared__ uint32_t Bs[128][36];   // [n][k]
    int tid = threadIdx.x, lane = tid & 31, wid = tid >> 5;
    int wm = wid & 3, wn = wid >> 2;   // warp tile: rows wm*32, cols wn*64
    int row0 = blockIdx.y * 128, col0 = blockIdx.x * 128;
    int fr = tid >> 3;                 // fill row base 0..31
    int fc = (tid & 7) * 4;            // fill k offset

    float c[2][8][4] = {};
    float4 ra[4], rb[4];
#pragma unroll
    for (int i = 0; i < 4; i++) {
        ra[i] = __ldg((const float4*)&A[(size_t)(row0 + fr + i * 32) * K + fc]);
        rb[i] = __ldg((const float4*)&B[(size_t)(col0 + fr + i * 32) * K + fc]);
    }

    int nkt = K / 32;
    for (int kt = 0; kt < nkt; kt++) {
#pragma unroll
        for (int i = 0; i < 4; i++) {
            *(uint4*)&As[fr + i * 32][fc] = make_uint4(
                cvt_tf32(ra[i].x), cvt_tf32(ra[i].y), cvt_tf32(ra[i].z), cvt_tf32(ra[i].w));
            *(uint4*)&Bs[fr + i * 32][fc] = make_uint4(
                cvt_tf32(rb[i].x), cvt_tf32(rb[i].y), cvt_tf32(rb[i].z), cvt_tf32(rb[i].w));
        }
        __syncthreads();
        if (kt + 1 < nkt) {
            int k0 = (kt + 1) * 32;
#pragma unroll
            for (int i = 0; i < 4; i++) {
                ra[i] = __ldg((const float4*)&A[(size_t)(row0 + fr + i * 32) * K + k0 + fc]);
                rb[i] = __ldg((const float4*)&B[(size_t)(col0 + fr + i * 32) * K + k0 + fc]);
            }
        }
#pragma unroll
        for (int ks = 0; ks < 4; ks++) {
            int kk = ks * 8 + (lane & 3);
            int ar = wm * 32 + (lane >> 2);
            uint32_t a[2][4], b[8][2];
            a[0][0] = As[ar][kk];      a[0][1] = As[ar + 8][kk];
            a[0][2] = As[ar][kk + 4];  a[0][3] = As[ar + 8][kk + 4];
            a[1][0] = As[ar + 16][kk];     a[1][1] = As[ar + 24][kk];
            a[1][2] = As[ar + 16][kk + 4]; a[1][3] = As[ar + 24][kk + 4];
#pragma unroll
            for (int n = 0; n < 8; n++) {
                int nb = wn * 64 + n * 8 + (lane >> 2);
                b[n][0] = Bs[nb][kk];
                b[n][1] = Bs[nb][kk + 4];
            }
#pragma unroll
            for (int t = 0; t < 2; t++)
#pragma unroll
                for (int n = 0; n < 8; n++)
                    mma_m16n8k8(c[t][n], a[t], b[n]);
        }
        __syncthreads();
    }
#pragma unroll
    for (int t = 0; t < 2; t++) {
        int row = row0 + wm * 32 + t * 16 + (lane >> 2);
#pragma unroll
        for (int n = 0; n < 8; n++) {
            int col = col0 + wn * 64 + n * 8 + (lane & 3) * 2;
            *(float2*)&C[(size_t)row * N + col]       = make_float2(c[t][n][0], c[t][n][1]);
            *(float2*)&C[(size_t)(row + 8) * N + col] = make_float2(c[t][n][2], c[t][n][3]);
        }
    }
}

// ---------------------------------------------------------------------------
// 4) transpose v -> g_vT[bh][d][k]  (k contiguous for B operand)
// ---------------------------------------------------------------------------
__global__ void transpose_v() {
    __shared__ float t[32][33];
    int k0 = blockIdx.x * 32, d0 = blockIdx.y * 32, bh = blockIdx.z;
    int b = bh >> 3, h = bh & 7;
    int tx = threadIdx.x, ty = threadIdx.y;
    const float* src = g_v + (size_t)b * Sc * Dc + h * HDc;
#pragma unroll
    for (int i = 0; i < 32; i += 8)
        t[ty + i][tx] = src[(size_t)(k0 + ty + i) * Dc + d0 + tx];
    __syncthreads();
    float* dst = g_vT + (size_t)bh * HDc * Sc;
#pragma unroll
    for (int i = 0; i < 32; i += 8)
        dst[(size_t)(d0 + ty + i) * Sc + k0 + tx] = t[tx][ty + i];
}

// ---------------------------------------------------------------------------
// 5) Fused attention with tf32 mma.sync P@V.
//    256 threads; q-tile 128, k-tile 32. Thread t: q = t/2, k-half = (t&1)*16.
//    w = exp(min(mq*mk*inv_dsq, 50)), rounded to tf32; lsum uses the SAME
//    rounded values as the MMA numerator.
// ---------------------------------------------------------------------------
__global__ __launch_bounds__(256) void attn_tf32() {
    __shared__ uint32_t Ws[128][36];   // [q][k]
    __shared__ uint32_t Vs[128][36];   // [d][k]
    __shared__ float s_red[256];
    __shared__ float s_sum[128];

    int tid = threadIdx.x, lane = tid & 31, wid = tid >> 5;
    int wm = wid & 3, wn = wid >> 2;
    int bh = blockIdx.y;
    int b = bh >> 3, h = bh & 7;
    int q0 = blockIdx.x * 128;

    int myq = tid >> 1;
    int kh  = (tid & 1) * 16;
    const float* mrow = g_masses + bh * Sc;
    const float* drow = g_inv_dsq + (size_t)(q0 + myq) * Sc;
    const float* vt   = g_vT + (size_t)bh * HDc * Sc;
    float mq = mrow[q0 + myq];
    float lsum = 0.0f;

    int fr = tid >> 3;
    int fc = (tid & 7) * 4;

    float c[2][8][4] = {};
    float4 rv[4], iv[4], mk[4];
#pragma unroll
    for (int i = 0; i < 4; i++)
        rv[i] = __ldg((const float4*)&vt[(size_t)(fr + i * 32) * Sc + fc]);
#pragma unroll
    for (int j = 0; j < 4; j++) {
        iv[j] = __ldg((const float4*)&drow[kh + j * 4]);
        mk[j] = __ldg((const float4*)&mrow[kh + j * 4]);
    }

    constexpr int NKT = Sc / 32;
    for (int kt = 0; kt < NKT; kt++) {
        // scores -> tf32 -> Ws ; lsum from the rounded values
#pragma unroll
        for (int j = 0; j < 4; j++) {
            uint4 wq;
            wq.x = cvt_tf32(__expf(fminf(mq * mk[j].x * iv[j].x, 50.0f)));
            wq.y = cvt_tf32(__expf(fminf(mq * mk[j].y * iv[j].y, 50.0f)));
            wq.z = cvt_tf32(__expf(fminf(mq * mk[j].z * iv[j].z, 50.0f)));
            wq.w = cvt_tf32(__expf(fminf(mq * mk[j].w * iv[j].w, 50.0f)));
            lsum += (__uint_as_float(wq.x) + __uint_as_float(wq.y)) +
                    (__uint_as_float(wq.z) + __uint_as_float(wq.w));
            *(uint4*)&Ws[myq][kh + j * 4] = wq;
        }
#pragma unroll
        for (int i = 0; i < 4; i++)
            *(uint4*)&Vs[fr + i * 32][fc] = make_uint4(
                cvt_tf32(rv[i].x), cvt_tf32(rv[i].y), cvt_tf32(rv[i].z), cvt_tf32(rv[i].w));
        __syncthreads();
        if (kt + 1 < NKT) {
            int k0 = (kt + 1) * 32;
#pragma unroll
            for (int i = 0; i < 4; i++)
                rv[i] = __ldg((const float4*)&vt[(size_t)(fr + i * 32) * Sc + k0 + fc]);
#pragma unroll
            for (int j = 0; j < 4; j++) {
                iv[j] = __ldg((const float4*)&drow[k0 + kh + j * 4]);
                mk[j] = __ldg((const float4*)&mrow[k0 + kh + j * 4]);
            }
        }
#pragma unroll
        for (int ks = 0; ks < 4; ks++) {
            int kk = ks * 8 + (lane & 3);
            int ar = wm * 32 + (lane >> 2);
            uint32_t a[2][4], bfr[8][2];
            a[0][0] = Ws[ar][kk];      a[0][1] = Ws[ar + 8][kk];
            a[0][2] = Ws[ar][kk + 4];  a[0][3] = Ws[ar + 8][kk + 4];
            a[1][0] = Ws[ar + 16][kk];     a[1][1] = Ws[ar + 24][kk];
            a[1][2] = Ws[ar + 16][kk + 4]; a[1][3] = Ws[ar + 24][kk + 4];
#pragma unroll
            for (int n = 0; n < 8; n++) {
                int nb = wn * 64 + n * 8 + (lane >> 2);
                bfr[n][0] = Vs[nb][kk];
                bfr[n][1] = Vs[nb][kk + 4];
            }
#pragma unroll
            for (int t = 0; t < 2; t++)
#pragma unroll
                for (int n = 0; n < 8; n++)
                    mma_m16n8k8(c[t][n], a[t], bfr[n]);
        }
        __syncthreads();
    }

    // row sums: 2 threads per q
    s_red[tid] = lsum;
    __syncthreads();
    if (tid < 128) s_sum[tid] = s_red[2 * tid] + s_red[2 * tid + 1];
    __syncthreads();

    // normalize + write head_out
#pragma unroll
    for (int t = 0; t < 2; t++) {
        int rl = wm * 32 + t * 16 + (lane >> 2);
        float r0 = 1.0f / s_sum[rl];
        float r1 = 1.0f / s_sum[rl + 8];
        float* o0 = g_ho + ((size_t)(b * Sc + q0 + rl)) * Dc + h * HDc;
        float* o1 = g_ho + ((size_t)(b * Sc + q0 + rl + 8)) * Dc + h * HDc;
#pragma unroll
        for (int n = 0; n < 8; n++) {
            int col = wn * 64 + n * 8 + (lane & 3) * 2;
            *(float2*)&o0[col] = make_float2(c[t][n][0] * r0, c[t][n][1] * r0);
            *(float2*)&o1[col] = make_float2(c[t][n][2] * r1, c[t][n][3] * r1);
        }
    }
}

// ---------------------------------------------------------------------------
extern "C" void kernel_launch(void* const* d_in, const int* in_sizes, int n_in,
                              void* d_out, int out_size) {
    const float* x      = (const float*)d_in[0];
    const float* mass_w = (const float*)d_in[1];
    const float* v_w    = (const float*)d_in[2];
    const float* out_w  = (const float*)d_in[3];
    const float* pos    = (const float*)d_in[4];
    float* out = (float*)d_out;

    void* pv = nullptr;
    void* pho = nullptr;
    cudaGetSymbolAddress(&pv, g_v);
    cudaGetSymbolAddress(&pho, g_ho);

    dist_kernel<<<dim3(Sc / 256, Sc), 256>>>(pos);
    masses_kernel<<<(Bc * Hc * Sc) / 8, 256>>>(x, mass_w);
    gemm_tf32<<<dim3(Dc / 128, (Bc * Sc) / 128), 256>>>(x, v_w, (float*)pv, Dc, Dc);
    transpose_v<<<dim3(Sc / 32, HDc / 32, Bc * Hc), dim3(32, 8)>>>();
    attn_tf32<<<dim3(Sc / 128, Bc * Hc), 256>>>();
    gemm_tf32<<<dim3(Dc / 128, (Bc * Sc) / 128), 256>>>((const float*)pho, out_w, out, Dc, Dc);
}

// round 4
// speedup vs baseline: 2.7501x; 1.1937x over previous
#include <cuda_runtime.h>
#include <cstdint>
#include <math.h>

// Problem shape (fixed by setup_inputs)
constexpr int Bc  = 2;
constexpr int Sc  = 2048;
constexpr int Dc  = 1024;
constexpr int Hc  = 8;
constexpr int HDc = 128;

// Scratch (no allocations allowed). tf32 operands stored as uint32 bit patterns.
__device__ __align__(256) float    g_inv_dsq[(size_t)Sc * Sc];       // 16 MB
__device__ __align__(256) float    g_masses[Bc * Hc * Sc];           // 128 KB
__device__ __align__(256) uint32_t g_xt[(size_t)Bc * Sc * Dc];       // 16 MB  x as tf32
__device__ __align__(256) uint32_t g_vwt[(size_t)Dc * Dc];           // 4 MB   v_w as tf32
__device__ __align__(256) uint32_t g_owt[(size_t)Dc * Dc];           // 4 MB   out_w as tf32
__device__ __align__(256) float    g_v[(size_t)Bc * Sc * Dc];        // 32 MB
__device__ __align__(256) uint32_t g_vT[(size_t)Bc * Hc * HDc * Sc]; // 32 MB [bh][d][k] tf32
__device__ __align__(256) uint32_t g_ho[(size_t)Bc * Sc * Dc];       // 32 MB head_out tf32

// ---------------------------------------------------------------------------
// helpers
// ---------------------------------------------------------------------------
__device__ __forceinline__ uint32_t smem_u32(const void* p) {
    uint32_t a;
    asm("{ .reg .u64 t; cvta.to.shared.u64 t, %1; cvt.u32.u64 %0, t; }"
        : "=r"(a) : "l"(p));
    return a;
}
__device__ __forceinline__ uint32_t cvt_tf32(float x) {
    uint32_t r;
    asm("cvt.rna.tf32.f32 %0, %1;" : "=r"(r) : "f"(x));
    return r;
}
__device__ __forceinline__ void mma_m16n8k8(float c[4], const uint32_t a[4],
                                            const uint32_t b[2]) {
    asm volatile(
        "mma.sync.aligned.m16n8k8.row.col.f32.tf32.tf32.f32 "
        "{%0,%1,%2,%3}, {%4,%5,%6,%7}, {%8,%9}, {%0,%1,%2,%3};"
        : "+f"(c[0]), "+f"(c[1]), "+f"(c[2]), "+f"(c[3])
        : "r"(a[0]), "r"(a[1]), "r"(a[2]), "r"(a[3]), "r"(b[0]), "r"(b[1]));
}
__device__ __forceinline__ void ldsm4(uint32_t& r0, uint32_t& r1, uint32_t& r2,
                                      uint32_t& r3, uint32_t addr) {
    asm volatile("ldmatrix.sync.aligned.m8n8.x4.shared.b16 {%0,%1,%2,%3}, [%4];"
                 : "=r"(r0), "=r"(r1), "=r"(r2), "=r"(r3) : "r"(addr));
}
__device__ __forceinline__ void cp16(uint32_t dst, const void* src) {
    asm volatile("cp.async.cg.shared.global [%0], [%1], 16;" :: "r"(dst), "l"(src));
}
#define CP_COMMIT() asm volatile("cp.async.commit_group;" ::: "memory")
#define CP_WAIT1()  asm volatile("cp.async.wait_group 1;" ::: "memory")

constexpr int STRD  = 36;          // padded row stride (words) -> conflict-free LDSM
constexpr int TILEW = 128 * STRD;  // words per 128x32 operand tile

// ---------------------------------------------------------------------------
// 1) inv_dsq[q][k] = 1 / (d'(q,k)^2 + 1e-6)
// ---------------------------------------------------------------------------
__global__ void dist_kernel(const float* __restrict__ pos) {
    int q = blockIdx.y;
    int k = blockIdx.x * blockDim.x + threadIdx.x;
    float acc = 1e-12f;
#pragma unroll
    for (int j = 0; j < 8; j++) {
        float d = pos[q * 8 + j] - pos[k * 8 + j];
        acc = fmaf(d, d, acc);
    }
    float dist = sqrtf(acc);
    dist = dist * (1.0f + 0.15f * sinf(dist));
    dist = fmaxf(dist, 0.0f);
    float dsq = fmaf(dist, dist, 1e-6f);
    g_inv_dsq[(size_t)q * Sc + k] = 1.0f / dsq;
}

// ---------------------------------------------------------------------------
// 2) masses[bh][s] = sigmoid( x[b,s,h*128:] . mass_w[h,:] )   (full fp32 x)
// ---------------------------------------------------------------------------
__global__ __launch_bounds__(256) void masses_kernel(const float* __restrict__ x,
                                                     const float* __restrict__ mw) {
    int gw   = blockIdx.x * 8 + (threadIdx.x >> 5);
    int lane = threadIdx.x & 31;
    int bh = gw / Sc;
    int s  = gw % Sc;
    int b = bh >> 3, h = bh & 7;
    const float4* xp = (const float4*)(x + ((size_t)(b * Sc + s)) * Dc + h * HDc);
    const float4* wp = (const float4*)(mw + h * HDc);
    float4 a = xp[lane];
    float4 w = wp[lane];
    float dot = a.x * w.x + a.y * w.y + a.z * w.z + a.w * w.w;
#pragma unroll
    for (int o = 16; o; o >>= 1) dot += __shfl_xor_sync(0xffffffffu, dot, o);
    if (lane == 0) g_masses[bh * Sc + s] = 1.0f / (1.0f + __expf(-dot));
}

// ---------------------------------------------------------------------------
// 3) f32 -> tf32-bits conversion pass (vectorized)
// ---------------------------------------------------------------------------
__global__ __launch_bounds__(256) void cvt_kernel(const float* __restrict__ in,
                                                  uint32_t* __restrict__ out, int n4) {
    int i = blockIdx.x * blockDim.x + threadIdx.x;
    if (i < n4) {
        float4 v = __ldg((const float4*)in + i);
        ((uint4*)out)[i] = make_uint4(cvt_tf32(v.x), cvt_tf32(v.y),
                                      cvt_tf32(v.z), cvt_tf32(v.w));
    }
}

// ---------------------------------------------------------------------------
// 4/7) tf32 GEMM: C[M,N] = A[M,K] * B[N,K]^T, operands pre-converted tf32 bits.
//      128x128 tile, BK=32, 256 thr (8 warps 4x2), cp.async 3-stage, ldmatrix.
// ---------------------------------------------------------------------------
__global__ __launch_bounds__(256, 2) void gemm_tf32(const uint32_t* __restrict__ A,
                                                    const uint32_t* __restrict__ B,
                                                    float* __restrict__ C,
                                                    int N, int K) {
    extern __shared__ uint32_t sm[];
    int tid = threadIdx.x, lane = tid & 31, wid = tid >> 5;
    int wm = wid & 3, wn = wid >> 2;
    int row0 = blockIdx.y * 128, col0 = blockIdx.x * 128;
    int fr = tid >> 3, fc = (tid & 7) * 4;
    uint32_t sbase = smem_u32(sm);

    // LDSM lane offsets (word units, stage-relative)
    int r = lane & 7, m = lane >> 3;
    int aoff[2], boff[4];
#pragma unroll
    for (int t = 0; t < 2; t++)
        aoff[t] = (wm * 32 + t * 16 + (m & 1) * 8 + r) * STRD + (m >> 1) * 4;
#pragma unroll
    for (int j = 0; j < 4; j++)
        boff[j] = (wn * 64 + (2 * j + (m >> 1)) * 8 + r) * STRD + (m & 1) * 4;

    float c[2][8][4] = {};
    int nkt = K / 32;

    const uint32_t* Ap = A + (size_t)(row0 + fr) * K + fc;
    const uint32_t* Bp = B + (size_t)(col0 + fr) * K + fc;

#pragma unroll
    for (int s = 0; s < 2; s++) {   // prologue: stages 0,1
        uint32_t ast = sbase + (s * 2 * TILEW) * 4;
        uint32_t bst = ast + TILEW * 4;
#pragma unroll
        for (int i = 0; i < 4; i++) {
            cp16(ast + ((fr + i * 32) * STRD + fc) * 4, Ap + (size_t)i * 32 * K + s * 32);
            cp16(bst + ((fr + i * 32) * STRD + fc) * 4, Bp + (size_t)i * 32 * K + s * 32);
        }
        CP_COMMIT();
    }

    for (int kt = 0; kt < nkt; kt++) {
        CP_WAIT1();
        __syncthreads();
        if (kt + 2 < nkt) {
            int s = (kt + 2) % 3, k0 = (kt + 2) * 32;
            uint32_t ast = sbase + (s * 2 * TILEW) * 4;
            uint32_t bst = ast + TILEW * 4;
#pragma unroll
            for (int i = 0; i < 4; i++) {
                cp16(ast + ((fr + i * 32) * STRD + fc) * 4, Ap + (size_t)i * 32 * K + k0);
                cp16(bst + ((fr + i * 32) * STRD + fc) * 4, Bp + (size_t)i * 32 * K + k0);
            }
        }
        CP_COMMIT();
        uint32_t sa = sbase + ((kt % 3) * 2 * TILEW) * 4;
        uint32_t sb = sa + TILEW * 4;
#pragma unroll
        for (int ks = 0; ks < 4; ks++) {
            uint32_t a[2][4], b[8][2];
#pragma unroll
            for (int t = 0; t < 2; t++)
                ldsm4(a[t][0], a[t][1], a[t][2], a[t][3], sa + (aoff[t] + ks * 8) * 4);
#pragma unroll
            for (int j = 0; j < 4; j++)
                ldsm4(b[2 * j][0], b[2 * j][1], b[2 * j + 1][0], b[2 * j + 1][1],
                      sb + (boff[j] + ks * 8) * 4);
#pragma unroll
            for (int t = 0; t < 2; t++)
#pragma unroll
                for (int n = 0; n < 8; n++)
                    mma_m16n8k8(c[t][n], a[t], b[n]);
        }
    }

#pragma unroll
    for (int t = 0; t < 2; t++) {
        int row = row0 + wm * 32 + t * 16 + (lane >> 2);
#pragma unroll
        for (int n = 0; n < 8; n++) {
            int col = col0 + wn * 64 + n * 8 + (lane & 3) * 2;
            *(float2*)&C[(size_t)row * N + col]       = make_float2(c[t][n][0], c[t][n][1]);
            *(float2*)&C[(size_t)(row + 8) * N + col] = make_float2(c[t][n][2], c[t][n][3]);
        }
    }
}

// ---------------------------------------------------------------------------
// 5) transpose v -> g_vT[bh][d][k], converting to tf32 bits
// ---------------------------------------------------------------------------
__global__ void transpose_v() {
    __shared__ float t[32][33];
    int k0 = blockIdx.x * 32, d0 = blockIdx.y * 32, bh = blockIdx.z;
    int b = bh >> 3, h = bh & 7;
    int tx = threadIdx.x, ty = threadIdx.y;
    const float* src = g_v + (size_t)b * Sc * Dc + h * HDc;
#pragma unroll
    for (int i = 0; i < 32; i += 8)
        t[ty + i][tx] = src[(size_t)(k0 + ty + i) * Dc + d0 + tx];
    __syncthreads();
    uint32_t* dst = g_vT + (size_t)bh * HDc * Sc;
#pragma unroll
    for (int i = 0; i < 32; i += 8)
        dst[(size_t)(d0 + ty + i) * Sc + k0 + tx] = cvt_tf32(t[tx][ty + i]);
}

// ---------------------------------------------------------------------------
// 6) Fused attention. q-tile 128, k-tile 32, 256 threads.
//    Ws (scores, tf32) double-buffered via STS; Vs 3-stage cp.async from g_vT.
//    smem: Ws[2], Vs[3] tiles + reduction arrays (dynamic).
// ---------------------------------------------------------------------------
__global__ __launch_bounds__(256, 2) void attn_tf32() {
    extern __shared__ uint32_t sm[];
    uint32_t* Ws = sm;                    // 2 tiles
    uint32_t* Vs = sm + 2 * TILEW;        // 3 tiles
    float* red = (float*)(sm + 5 * TILEW);
    float* ssum = red + 256;

    int tid = threadIdx.x, lane = tid & 31, wid = tid >> 5;
    int wm = wid & 3, wn = wid >> 2;
    int bh = blockIdx.y;
    int b = bh >> 3, h = bh & 7;
    int q0 = blockIdx.x * 128;
    int fr = tid >> 3, fc = (tid & 7) * 4;
    uint32_t sbase = smem_u32(sm);
    uint32_t vbase = sbase + (2 * TILEW) * 4;

    int r = lane & 7, m = lane >> 3;
    int aoff[2], boff[4];
#pragma unroll
    for (int t = 0; t < 2; t++)
        aoff[t] = (wm * 32 + t * 16 + (m & 1) * 8 + r) * STRD + (m >> 1) * 4;
#pragma unroll
    for (int j = 0; j < 4; j++)
        boff[j] = (wn * 64 + (2 * j + (m >> 1)) * 8 + r) * STRD + (m & 1) * 4;

    int myq = tid >> 1;
    int kh  = (tid & 1) * 16;
    const float* mrow = g_masses + bh * Sc;
    const float* drow = g_inv_dsq + (size_t)(q0 + myq) * Sc;
    const uint32_t* vt = g_vT + (size_t)bh * HDc * Sc + (size_t)fr * Sc + fc;
    float mq = mrow[q0 + myq];
    float lsum = 0.0f;

    float c[2][8][4] = {};
    constexpr int NKT = Sc / 32;

    // prologue: V tiles 0,1 async; scores tile 0; iv regs for tile 1
#pragma unroll
    for (int s = 0; s < 2; s++) {
        uint32_t vst = vbase + s * TILEW * 4;
#pragma unroll
        for (int i = 0; i < 4; i++)
            cp16(vst + ((fr + i * 32) * STRD + fc) * 4, vt + (size_t)i * 32 * Sc + s * 32);
        CP_COMMIT();
    }
    float4 iv[4];
#pragma unroll
    for (int j = 0; j < 4; j++) iv[j] = __ldg((const float4*)&drow[kh + j * 4]);
    {
        uint32_t* wrow = Ws + myq * STRD + kh;
#pragma unroll
        for (int j = 0; j < 4; j++) {
            float4 mk = __ldg((const float4*)&mrow[kh + j * 4]);
            uint4 wq;
            wq.x = cvt_tf32(__expf(fminf(mq * mk.x * iv[j].x, 50.0f)));
            wq.y = cvt_tf32(__expf(fminf(mq * mk.y * iv[j].y, 50.0f)));
            wq.z = cvt_tf32(__expf(fminf(mq * mk.z * iv[j].z, 50.0f)));
            wq.w = cvt_tf32(__expf(fminf(mq * mk.w * iv[j].w, 50.0f)));
            lsum += (__uint_as_float(wq.x) + __uint_as_float(wq.y)) +
                    (__uint_as_float(wq.z) + __uint_as_float(wq.w));
            *(uint4*)&wrow[j * 4] = wq;
        }
    }
#pragma unroll
    for (int j = 0; j < 4; j++) iv[j] = __ldg((const float4*)&drow[32 + kh + j * 4]);

    for (int kt = 0; kt < NKT; kt++) {
        CP_WAIT1();
        __syncthreads();
        if (kt + 2 < NKT) {
            int s = (kt + 2) % 3, k0 = (kt + 2) * 32;
            uint32_t vst = vbase + s * TILEW * 4;
#pragma unroll
            for (int i = 0; i < 4; i++)
                cp16(vst + ((fr + i * 32) * STRD + fc) * 4, vt + (size_t)i * 32 * Sc + k0);
        }
        CP_COMMIT();
        if (kt + 1 < NKT) {
            int k0n = (kt + 1) * 32;
            uint32_t* wrow = Ws + ((kt + 1) & 1) * TILEW + myq * STRD + kh;
#pragma unroll
            for (int j = 0; j < 4; j++) {
                float4 mk = __ldg((const float4*)&mrow[k0n + kh + j * 4]);
                uint4 wq;
                wq.x = cvt_tf32(__expf(fminf(mq * mk.x * iv[j].x, 50.0f)));
                wq.y = cvt_tf32(__expf(fminf(mq * mk.y * iv[j].y, 50.0f)));
                wq.z = cvt_tf32(__expf(fminf(mq * mk.z * iv[j].z, 50.0f)));
                wq.w = cvt_tf32(__expf(fminf(mq * mk.w * iv[j].w, 50.0f)));
                lsum += (__uint_as_float(wq.x) + __uint_as_float(wq.y)) +
                        (__uint_as_float(wq.z) + __uint_as_float(wq.w));
                *(uint4*)&wrow[j * 4] = wq;
            }
            if (kt + 2 < NKT) {
                int k0p = (kt + 2) * 32;
#pragma unroll
                for (int j = 0; j < 4; j++)
                    iv[j] = __ldg((const float4*)&drow[k0p + kh + j * 4]);
            }
        }
        uint32_t sa = sbase + ((kt & 1) * TILEW) * 4;
        uint32_t sb = vbase + ((kt % 3) * TILEW) * 4;
#pragma unroll
        for (int ks = 0; ks < 4; ks++) {
            uint32_t a[2][4], bfr[8][2];
#pragma unroll
            for (int t = 0; t < 2; t++)
                ldsm4(a[t][0], a[t][1], a[t][2], a[t][3], sa + (aoff[t] + ks * 8) * 4);
#pragma unroll
            for (int j = 0; j < 4; j++)
                ldsm4(bfr[2 * j][0], bfr[2 * j][1], bfr[2 * j + 1][0], bfr[2 * j + 1][1],
                      sb + (boff[j] + ks * 8) * 4);
#pragma unroll
            for (int t = 0; t < 2; t++)
#pragma unroll
                for (int n = 0; n < 8; n++)
                    mma_m16n8k8(c[t][n], a[t], bfr[n]);
        }
    }

    red[tid] = lsum;
    __syncthreads();
    if (tid < 128) ssum[tid] = red[2 * tid] + red[2 * tid + 1];
    __syncthreads();

#pragma unroll
    for (int t = 0; t < 2; t++) {
        int rl = wm * 32 + t * 16 + (lane >> 2);
        float r0 = 1.0f / ssum[rl];
        float r1 = 1.0f / ssum[rl + 8];
        uint32_t* o0 = g_ho + ((size_t)(b * Sc + q0 + rl)) * Dc + h * HDc;
        uint32_t* o1 = g_ho + ((size_t)(b * Sc + q0 + rl + 8)) * Dc + h * HDc;
#pragma unroll
        for (int n = 0; n < 8; n++) {
            int col = wn * 64 + n * 8 + (lane & 3) * 2;
            *(uint2*)&o0[col] = make_uint2(cvt_tf32(c[t][n][0] * r0),
                                           cvt_tf32(c[t][n][1] * r0));
            *(uint2*)&o1[col] = make_uint2(cvt_tf32(c[t][n][2] * r1),
                                           cvt_tf32(c[t][n][3] * r1));
        }
    }
}

// ---------------------------------------------------------------------------
extern "C" void kernel_launch(void* const* d_in, const int* in_sizes, int n_in,
                              void* d_out, int out_size) {
    const float* x      = (const float*)d_in[0];
    const float* mass_w = (const float*)d_in[1];
    const float* v_w    = (const float*)d_in[2];
    const float* out_w  = (const float*)d_in[3];
    const float* pos    = (const float*)d_in[4];
    float* out = (float*)d_out;

    void *pxt = nullptr, *pvwt = nullptr, *powt = nullptr, *pv = nullptr, *pho = nullptr;
    cudaGetSymbolAddress(&pxt,  g_xt);
    cudaGetSymbolAddress(&pvwt, g_vwt);
    cudaGetSymbolAddress(&powt, g_owt);
    cudaGetSymbolAddress(&pv,   g_v);
    cudaGetSymbolAddress(&pho,  g_ho);

    const int GEMM_SMEM = 3 * 2 * TILEW * 4;                 // 110592 B
    const int ATTN_SMEM = 5 * TILEW * 4 + (256 + 128) * 4;   //  93696 B
    cudaFuncSetAttribute(gemm_tf32, cudaFuncAttributeMaxDynamicSharedMemorySize, GEMM_SMEM);
    cudaFuncSetAttribute(attn_tf32, cudaFuncAttributeMaxDynamicSharedMemorySize, ATTN_SMEM);

    dist_kernel<<<dim3(Sc / 256, Sc), 256>>>(pos);
    masses_kernel<<<(Bc * Hc * Sc) / 8, 256>>>(x, mass_w);
    cvt_kernel<<<(Bc * Sc * Dc / 4 + 255) / 256, 256>>>(x, (uint32_t*)pxt, Bc * Sc * Dc / 4);
    cvt_kernel<<<(Dc * Dc / 4 + 255) / 256, 256>>>(v_w, (uint32_t*)pvwt, Dc * Dc / 4);
    cvt_kernel<<<(Dc * Dc / 4 + 255) / 256, 256>>>(out_w, (uint32_t*)powt, Dc * Dc / 4);

    gemm_tf32<<<dim3(Dc / 128, (Bc * Sc) / 128), 256, GEMM_SMEM>>>(
        (const uint32_t*)pxt, (const uint32_t*)pvwt, (float*)pv, Dc, Dc);
    transpose_v<<<dim3(Sc / 32, HDc / 32, Bc * Hc), dim3(32, 8)>>>();
    attn_tf32<<<dim3(Sc / 128, Bc * Hc), 256, ATTN_SMEM>>>();
    gemm_tf32<<<dim3(Dc / 128, (Bc * Sc) / 128), 256, GEMM_SMEM>>>(
        (const uint32_t*)pho, (const uint32_t*)powt, out, Dc, Dc);
}

// round 5
// speedup vs baseline: 3.1761x; 1.1549x over previous
#include <cuda_runtime.h>
#include <cuda_fp16.h>
#include <cstdint>
#include <math.h>

// Problem shape (fixed by setup_inputs)
constexpr int Bc  = 2;
constexpr int Sc  = 2048;
constexpr int Dc  = 1024;
constexpr int Hc  = 8;
constexpr int HDc = 128;

// Scratch (no allocations allowed)
__device__ __align__(256) float    g_inv_dsq[(size_t)Sc * Sc];       // 16 MB
__device__ __align__(256) float    g_masses[Bc * Hc * Sc];           // 128 KB
__device__ __align__(256) __half   g_xh[(size_t)Bc * Sc * Dc];       // 8 MB   x fp16
__device__ __align__(256) __half   g_vwh[(size_t)Dc * Dc];           // 2 MB   v_w fp16
__device__ __align__(256) __half   g_owh[(size_t)Dc * Dc];           // 2 MB   out_w fp16
__device__ __align__(256) float    g_v[(size_t)Bc * Sc * Dc];        // 32 MB
__device__ __align__(256) uint32_t g_vT[(size_t)Bc * Hc * HDc * Sc]; // 32 MB [bh][d][k] tf32
__device__ __align__(256) __half   g_hoh[(size_t)Bc * Sc * Dc];      // 8 MB  head_out fp16

// ---------------------------------------------------------------------------
// helpers
// ---------------------------------------------------------------------------
__device__ __forceinline__ uint32_t smem_u32(const void* p) {
    uint32_t a;
    asm("{ .reg .u64 t; cvta.to.shared.u64 t, %1; cvt.u32.u64 %0, t; }"
        : "=r"(a) : "l"(p));
    return a;
}
__device__ __forceinline__ uint32_t cvt_tf32(float x) {
    uint32_t r;
    asm("cvt.rna.tf32.f32 %0, %1;" : "=r"(r) : "f"(x));
    return r;
}
__device__ __forceinline__ void mma_m16n8k8(float c[4], const uint32_t a[4],
                                            const uint32_t b[2]) {
    asm volatile(
        "mma.sync.aligned.m16n8k8.row.col.f32.tf32.tf32.f32 "
        "{%0,%1,%2,%3}, {%4,%5,%6,%7}, {%8,%9}, {%0,%1,%2,%3};"
        : "+f"(c[0]), "+f"(c[1]), "+f"(c[2]), "+f"(c[3])
        : "r"(a[0]), "r"(a[1]), "r"(a[2]), "r"(a[3]), "r"(b[0]), "r"(b[1]));
}
__device__ __forceinline__ void mma_m16n8k16f16(float c[4], const uint32_t a[4],
                                                const uint32_t b[2]) {
    asm volatile(
        "mma.sync.aligned.m16n8k16.row.col.f32.f16.f16.f32 "
        "{%0,%1,%2,%3}, {%4,%5,%6,%7}, {%8,%9}, {%0,%1,%2,%3};"
        : "+f"(c[0]), "+f"(c[1]), "+f"(c[2]), "+f"(c[3])
        : "r"(a[0]), "r"(a[1]), "r"(a[2]), "r"(a[3]), "r"(b[0]), "r"(b[1]));
}
__device__ __forceinline__ void ldsm4(uint32_t& r0, uint32_t& r1, uint32_t& r2,
                                      uint32_t& r3, uint32_t addr) {
    asm volatile("ldmatrix.sync.aligned.m8n8.x4.shared.b16 {%0,%1,%2,%3}, [%4];"
                 : "=r"(r0), "=r"(r1), "=r"(r2), "=r"(r3) : "r"(addr));
}
__device__ __forceinline__ void cp16(uint32_t dst, const void* src) {
    asm volatile("cp.async.cg.shared.global [%0], [%1], 16;" :: "r"(dst), "l"(src));
}
#define CP_COMMIT() asm volatile("cp.async.commit_group;" ::: "memory")
#define CP_WAIT1()  asm volatile("cp.async.wait_group 1;" ::: "memory")

constexpr int STRD  = 36;          // tf32 padded row stride (words)
constexpr int TILEW = 128 * STRD;  // words per 128x32 tf32 tile
constexpr int SH    = 40;          // fp16 padded row stride (halves) = 80B
constexpr int HTILE = 128 * SH;    // halves per 128x32 fp16 tile

// ---------------------------------------------------------------------------
// 1) inv_dsq[q][k] = 1 / (d'(q,k)^2 + 1e-6)
// ---------------------------------------------------------------------------
__global__ void dist_kernel(const float* __restrict__ pos) {
    int q = blockIdx.y;
    int k = blockIdx.x * blockDim.x + threadIdx.x;
    float acc = 1e-12f;
#pragma unroll
    for (int j = 0; j < 8; j++) {
        float d = pos[q * 8 + j] - pos[k * 8 + j];
        acc = fmaf(d, d, acc);
    }
    float dist = sqrtf(acc);
    dist = dist * (1.0f + 0.15f * sinf(dist));
    dist = fmaxf(dist, 0.0f);
    float dsq = fmaf(dist, dist, 1e-6f);
    g_inv_dsq[(size_t)q * Sc + k] = 1.0f / dsq;
}

// ---------------------------------------------------------------------------
// 2) masses[bh][s] = sigmoid( x[b,s,h*128:] . mass_w[h,:] )   (fp32 x)
// ---------------------------------------------------------------------------
__global__ __launch_bounds__(256) void masses_kernel(const float* __restrict__ x,
                                                     const float* __restrict__ mw) {
    int gw   = blockIdx.x * 8 + (threadIdx.x >> 5);
    int lane = threadIdx.x & 31;
    int bh = gw / Sc;
    int s  = gw % Sc;
    int b = bh >> 3, h = bh & 7;
    const float4* xp = (const float4*)(x + ((size_t)(b * Sc + s)) * Dc + h * HDc);
    const float4* wp = (const float4*)(mw + h * HDc);
    float4 a = xp[lane];
    float4 w = wp[lane];
    float dot = a.x * w.x + a.y * w.y + a.z * w.z + a.w * w.w;
#pragma unroll
    for (int o = 16; o; o >>= 1) dot += __shfl_xor_sync(0xffffffffu, dot, o);
    if (lane == 0) g_masses[bh * Sc + s] = 1.0f / (1.0f + __expf(-dot));
}

// ---------------------------------------------------------------------------
// 3) f32 -> fp16 conversion pass
// ---------------------------------------------------------------------------
__global__ __launch_bounds__(256) void cvt16_kernel(const float* __restrict__ in,
                                                    __half* __restrict__ out, int n4) {
    int i = blockIdx.x * blockDim.x + threadIdx.x;
    if (i < n4) {
        float4 v = __ldg((const float4*)in + i);
        __half2 h0 = __floats2half2_rn(v.x, v.y);
        __half2 h1 = __floats2half2_rn(v.z, v.w);
        uint2 u;
        *(__half2*)&u.x = h0;
        *(__half2*)&u.y = h1;
        ((uint2*)out)[i] = u;
    }
}

// ---------------------------------------------------------------------------
// 4/7) fp16 GEMM (fp32 accum): C[M,N] = A[M,K] * B[N,K]^T
//      128x128 tile, BK=32 (2 x k16), 256 thr (8 warps 4x2), cp.async 3-stage.
// ---------------------------------------------------------------------------
__global__ __launch_bounds__(256, 2) void gemm_fp16(const __half* __restrict__ A,
                                                    const __half* __restrict__ B,
                                                    float* __restrict__ C,
                                                    int N, int K) {
    extern __shared__ uint32_t sm[];
    int tid = threadIdx.x, lane = tid & 31, wid = tid >> 5;
    int wm = wid & 3, wn = wid >> 2;
    int row0 = blockIdx.y * 128, col0 = blockIdx.x * 128;
    int fr = tid >> 1;              // fill row 0..127
    int fc = (tid & 1) * 16;        // fill half-offset 0 / 16
    uint32_t sbase = smem_u32(sm);

    int r = lane & 7, m = lane >> 3;
    int aoff[2], boff[4];           // half units, stage-relative
#pragma unroll
    for (int t = 0; t < 2; t++)
        aoff[t] = (wm * 32 + t * 16 + (m & 1) * 8 + r) * SH + (m >> 1) * 8;
#pragma unroll
    for (int j = 0; j < 4; j++)
        boff[j] = (wn * 64 + j * 16 + (m & 1) * 8 + r) * SH + (m >> 1) * 8;

    float c[2][8][4] = {};
    int nkt = K / 32;

    const __half* Ap = A + (size_t)(row0 + fr) * K + fc;
    const __half* Bp = B + (size_t)(col0 + fr) * K + fc;

#pragma unroll
    for (int s = 0; s < 2; s++) {   // prologue stages 0,1
        uint32_t ast = sbase + (s * 2 * HTILE) * 2;
        uint32_t bst = ast + HTILE * 2;
        cp16(ast + (fr * SH + fc) * 2,       Ap + s * 32);
        cp16(ast + (fr * SH + fc + 8) * 2,   Ap + s * 32 + 8);
        cp16(bst + (fr * SH + fc) * 2,       Bp + s * 32);
        cp16(bst + (fr * SH + fc + 8) * 2,   Bp + s * 32 + 8);
        CP_COMMIT();
    }

    for (int kt = 0; kt < nkt; kt++) {
        CP_WAIT1();
        __syncthreads();
        if (kt + 2 < nkt) {
            int s = (kt + 2) % 3, k0 = (kt + 2) * 32;
            uint32_t ast = sbase + (s * 2 * HTILE) * 2;
            uint32_t bst = ast + HTILE * 2;
            cp16(ast + (fr * SH + fc) * 2,     Ap + k0);
            cp16(ast + (fr * SH + fc + 8) * 2, Ap + k0 + 8);
            cp16(bst + (fr * SH + fc) * 2,     Bp + k0);
            cp16(bst + (fr * SH + fc + 8) * 2, Bp + k0 + 8);
        }
        CP_COMMIT();
        uint32_t sa = sbase + ((kt % 3) * 2 * HTILE) * 2;
        uint32_t sb = sa + HTILE * 2;
#pragma unroll
        for (int ks = 0; ks < 2; ks++) {
            uint32_t a[2][4], bq[4][4];
#pragma unroll
            for (int t = 0; t < 2; t++)
                ldsm4(a[t][0], a[t][1], a[t][2], a[t][3], sa + (aoff[t] + ks * 16) * 2);
#pragma unroll
            for (int j = 0; j < 4; j++)
                ldsm4(bq[j][0], bq[j][1], bq[j][2], bq[j][3], sb + (boff[j] + ks * 16) * 2);
#pragma unroll
            for (int t = 0; t < 2; t++)
#pragma unroll
                for (int j = 0; j < 4; j++) {
                    uint32_t b0[2] = {bq[j][0], bq[j][2]};
                    uint32_t b1[2] = {bq[j][1], bq[j][3]};
                    mma_m16n8k16f16(c[t][2 * j],     a[t], b0);
                    mma_m16n8k16f16(c[t][2 * j + 1], a[t], b1);
                }
        }
    }

#pragma unroll
    for (int t = 0; t < 2; t++) {
        int row = row0 + wm * 32 + t * 16 + (lane >> 2);
#pragma unroll
        for (int n = 0; n < 8; n++) {
            int col = col0 + wn * 64 + n * 8 + (lane & 3) * 2;
            *(float2*)&C[(size_t)row * N + col]       = make_float2(c[t][n][0], c[t][n][1]);
            *(float2*)&C[(size_t)(row + 8) * N + col] = make_float2(c[t][n][2], c[t][n][3]);
        }
    }
}

// ---------------------------------------------------------------------------
// 5) transpose v -> g_vT[bh][d][k], converting to tf32 bits
// ---------------------------------------------------------------------------
__global__ void transpose_v() {
    __shared__ float t[32][33];
    int k0 = blockIdx.x * 32, d0 = blockIdx.y * 32, bh = blockIdx.z;
    int b = bh >> 3, h = bh & 7;
    int tx = threadIdx.x, ty = threadIdx.y;
    const float* src = g_v + (size_t)b * Sc * Dc + h * HDc;
#pragma unroll
    for (int i = 0; i < 32; i += 8)
        t[ty + i][tx] = src[(size_t)(k0 + ty + i) * Dc + d0 + tx];
    __syncthreads();
    uint32_t* dst = g_vT + (size_t)bh * HDc * Sc;
#pragma unroll
    for (int i = 0; i < 32; i += 8)
        dst[(size_t)(d0 + ty + i) * Sc + k0 + tx] = cvt_tf32(t[tx][ty + i]);
}

// ---------------------------------------------------------------------------
// 6) Fused attention (tf32 mma, fp32 accum). q-tile 128, k-tile 32, 256 thr.
//    Ws (scores) double-buffered STS; Vs 3-stage cp.async from g_vT.
//    Epilogue writes head_out as fp16 (feeds fp16 out-GEMM).
// ---------------------------------------------------------------------------
__global__ __launch_bounds__(256, 2) void attn_tf32() {
    extern __shared__ uint32_t sm[];
    uint32_t* Ws = sm;                    // 2 tiles
    float* red = (float*)(sm + 5 * TILEW);
    float* ssum = red + 256;

    int tid = threadIdx.x, lane = tid & 31, wid = tid >> 5;
    int wm = wid & 3, wn = wid >> 2;
    int bh = blockIdx.y;
    int b = bh >> 3, h = bh & 7;
    int q0 = blockIdx.x * 128;
    int fr = tid >> 3, fc = (tid & 7) * 4;
    uint32_t sbase = smem_u32(sm);
    uint32_t vbase = sbase + (2 * TILEW) * 4;

    int r = lane & 7, m = lane >> 3;
    int aoff[2], boff[4];
#pragma unroll
    for (int t = 0; t < 2; t++)
        aoff[t] = (wm * 32 + t * 16 + (m & 1) * 8 + r) * STRD + (m >> 1) * 4;
#pragma unroll
    for (int j = 0; j < 4; j++)
        boff[j] = (wn * 64 + (2 * j + (m >> 1)) * 8 + r) * STRD + (m & 1) * 4;

    int myq = tid >> 1;
    int kh  = (tid & 1) * 16;
    const float* mrow = g_masses + bh * Sc;
    const float* drow = g_inv_dsq + (size_t)(q0 + myq) * Sc;
    const uint32_t* vt = g_vT + (size_t)bh * HDc * Sc + (size_t)fr * Sc + fc;
    float mq = mrow[q0 + myq];
    float lsum = 0.0f;

    float c[2][8][4] = {};
    constexpr int NKT = Sc / 32;

    // prologue: V tiles 0,1 async; scores tile 0; iv regs for tile 1
#pragma unroll
    for (int s = 0; s < 2; s++) {
        uint32_t vst = vbase + s * TILEW * 4;
#pragma unroll
        for (int i = 0; i < 4; i++)
            cp16(vst + ((fr + i * 32) * STRD + fc) * 4, vt + (size_t)i * 32 * Sc + s * 32);
        CP_COMMIT();
    }
    float4 iv[4];
#pragma unroll
    for (int j = 0; j < 4; j++) iv[j] = __ldg((const float4*)&drow[kh + j * 4]);
    {
        uint32_t* wrow = Ws + myq * STRD + kh;
#pragma unroll
        for (int j = 0; j < 4; j++) {
            float4 mk = __ldg((const float4*)&mrow[kh + j * 4]);
            uint4 wq;
            wq.x = cvt_tf32(__expf(fminf(mq * mk.x * iv[j].x, 50.0f)));
            wq.y = cvt_tf32(__expf(fminf(mq * mk.y * iv[j].y, 50.0f)));
            wq.z = cvt_tf32(__expf(fminf(mq * mk.z * iv[j].z, 50.0f)));
            wq.w = cvt_tf32(__expf(fminf(mq * mk.w * iv[j].w, 50.0f)));
            lsum += (__uint_as_float(wq.x) + __uint_as_float(wq.y)) +
                    (__uint_as_float(wq.z) + __uint_as_float(wq.w));
            *(uint4*)&wrow[j * 4] = wq;
        }
    }
#pragma unroll
    for (int j = 0; j < 4; j++) iv[j] = __ldg((const float4*)&drow[32 + kh + j * 4]);

    for (int kt = 0; kt < NKT; kt++) {
        CP_WAIT1();
        __syncthreads();
        if (kt + 2 < NKT) {
            int s = (kt + 2) % 3, k0 = (kt + 2) * 32;
            uint32_t vst = vbase + s * TILEW * 4;
#pragma unroll
            for (int i = 0; i < 4; i++)
                cp16(vst + ((fr + i * 32) * STRD + fc) * 4, vt + (size_t)i * 32 * Sc + k0);
        }
        CP_COMMIT();
        if (kt + 1 < NKT) {
            int k0n = (kt + 1) * 32;
            uint32_t* wrow = Ws + ((kt + 1) & 1) * TILEW + myq * STRD + kh;
#pragma unroll
            for (int j = 0; j < 4; j++) {
                float4 mk = __ldg((const float4*)&mrow[k0n + kh + j * 4]);
                uint4 wq;
                wq.x = cvt_tf32(__expf(fminf(mq * mk.x * iv[j].x, 50.0f)));
                wq.y = cvt_tf32(__expf(fminf(mq * mk.y * iv[j].y, 50.0f)));
                wq.z = cvt_tf32(__expf(fminf(mq * mk.z * iv[j].z, 50.0f)));
                wq.w = cvt_tf32(__expf(fminf(mq * mk.w * iv[j].w, 50.0f)));
                lsum += (__uint_as_float(wq.x) + __uint_as_float(wq.y)) +
                        (__uint_as_float(wq.z) + __uint_as_float(wq.w));
                *(uint4*)&wrow[j * 4] = wq;
            }
            if (kt + 2 < NKT) {
                int k0p = (kt + 2) * 32;
#pragma unroll
                for (int j = 0; j < 4; j++)
                    iv[j] = __ldg((const float4*)&drow[k0p + kh + j * 4]);
            }
        }
        uint32_t sa = sbase + ((kt & 1) * TILEW) * 4;
        uint32_t sb = vbase + ((kt % 3) * TILEW) * 4;
#pragma unroll
        for (int ks = 0; ks < 4; ks++) {
            uint32_t a[2][4], bfr[8][2];
#pragma unroll
            for (int t = 0; t < 2; t++)
                ldsm4(a[t][0], a[t][1], a[t][2], a[t][3], sa + (aoff[t] + ks * 8) * 4);
#pragma unroll
            for (int j = 0; j < 4; j++)
                ldsm4(bfr[2 * j][0], bfr[2 * j][1], bfr[2 * j + 1][0], bfr[2 * j + 1][1],
                      sb + (boff[j] + ks * 8) * 4);
#pragma unroll
            for (int t = 0; t < 2; t++)
#pragma unroll
                for (int n = 0; n < 8; n++)
                    mma_m16n8k8(c[t][n], a[t], bfr[n]);
        }
    }

    red[tid] = lsum;
    __syncthreads();
    if (tid < 128) ssum[tid] = red[2 * tid] + red[2 * tid + 1];
    __syncthreads();

#pragma unroll
    for (int t = 0; t < 2; t++) {
        int rl = wm * 32 + t * 16 + (lane >> 2);
        float r0 = 1.0f / ssum[rl];
        float r1 = 1.0f / ssum[rl + 8];
        __half* o0 = g_hoh + ((size_t)(b * Sc + q0 + rl)) * Dc + h * HDc;
        __half* o1 = g_hoh + ((size_t)(b * Sc + q0 + rl + 8)) * Dc + h * HDc;
#pragma unroll
        for (int n = 0; n < 8; n++) {
            int col = wn * 64 + n * 8 + (lane & 3) * 2;
            *(__half2*)&o0[col] = __floats2half2_rn(c[t][n][0] * r0, c[t][n][1] * r0);
            *(__half2*)&o1[col] = __floats2half2_rn(c[t][n][2] * r1, c[t][n][3] * r1);
        }
    }
}

// ---------------------------------------------------------------------------
extern "C" void kernel_launch(void* const* d_in, const int* in_sizes, int n_in,
                              void* d_out, int out_size) {
    const float* x      = (const float*)d_in[0];
    const float* mass_w = (const float*)d_in[1];
    const float* v_w    = (const float*)d_in[2];
    const float* out_w  = (const float*)d_in[3];
    const float* pos    = (const float*)d_in[4];
    float* out = (float*)d_out;

    void *pxh = nullptr, *pvwh = nullptr, *powh = nullptr, *pv = nullptr, *phoh = nullptr;
    cudaGetSymbolAddress(&pxh,  g_xh);
    cudaGetSymbolAddress(&pvwh, g_vwh);
    cudaGetSymbolAddress(&powh, g_owh);
    cudaGetSymbolAddress(&pv,   g_v);
    cudaGetSymbolAddress(&phoh, g_hoh);

    const int GEMM_SMEM = 3 * 2 * HTILE * 2;                 // 61440 B
    const int ATTN_SMEM = 5 * TILEW * 4 + (256 + 128) * 4;   // 93696 B
    cudaFuncSetAttribute(gemm_fp16, cudaFuncAttributeMaxDynamicSharedMemorySize, GEMM_SMEM);
    cudaFuncSetAttribute(attn_tf32, cudaFuncAttributeMaxDynamicSharedMemorySize, ATTN_SMEM);

    dist_kernel<<<dim3(Sc / 256, Sc), 256>>>(pos);
    masses_kernel<<<(Bc * Hc * Sc) / 8, 256>>>(x, mass_w);
    cvt16_kernel<<<(Bc * Sc * Dc / 4 + 255) / 256, 256>>>(x, (__half*)pxh, Bc * Sc * Dc / 4);
    cvt16_kernel<<<(Dc * Dc / 4 + 255) / 256, 256>>>(v_w, (__half*)pvwh, Dc * Dc / 4);
    cvt16_kernel<<<(Dc * Dc / 4 + 255) / 256, 256>>>(out_w, (__half*)powh, Dc * Dc / 4);

    gemm_fp16<<<dim3(Dc / 128, (Bc * Sc) / 128), 256, GEMM_SMEM>>>(
        (const __half*)pxh, (const __half*)pvwh, (float*)pv, Dc, Dc);
    transpose_v<<<dim3(Sc / 32, HDc / 32, Bc * Hc), dim3(32, 8)>>>();
    attn_tf32<<<dim3(Sc / 128, Bc * Hc), 256, ATTN_SMEM>>>();
    gemm_fp16<<<dim3(Dc / 128, (Bc * Sc) / 128), 256, GEMM_SMEM>>>(
        (const __half*)phoh, (const __half*)powh, out, Dc, Dc);
}

// round 6
// speedup vs baseline: 3.3081x; 1.0416x over previous
#include <cuda_runtime.h>
#include <cuda_fp16.h>
#include <cstdint>
#include <math.h>

// Problem shape (fixed by setup_inputs)
constexpr int Bc  = 2;
constexpr int Sc  = 2048;
constexpr int Dc  = 1024;
constexpr int Hc  = 8;
constexpr int HDc = 128;

// Scratch (no allocations allowed)
__device__ __align__(256) float    g_inv_dsq[(size_t)Sc * Sc];       // 16 MB
__device__ __align__(256) float    g_masses[Bc * Hc * Sc];           // 128 KB
__device__ __align__(256) float    g_rowmax[Bc * Hc * Sc];           // 128 KB
__device__ __align__(256) __half   g_xh[(size_t)Bc * Sc * Dc];       // 8 MB   x fp16
__device__ __align__(256) __half   g_vwh[(size_t)Dc * Dc];           // 2 MB   v_w fp16
__device__ __align__(256) __half   g_owh[(size_t)Dc * Dc];           // 2 MB   out_w fp16
__device__ __align__(256) float    g_v[(size_t)Bc * Sc * Dc];        // 32 MB
__device__ __align__(256) __half   g_vTh[(size_t)Bc * Hc * HDc * Sc];// 16 MB [bh][d][k] fp16
__device__ __align__(256) __half   g_hoh[(size_t)Bc * Sc * Dc];      // 8 MB  head_out fp16

// ---------------------------------------------------------------------------
// helpers
// ---------------------------------------------------------------------------
__device__ __forceinline__ uint32_t smem_u32(const void* p) {
    uint32_t a;
    asm("{ .reg .u64 t; cvta.to.shared.u64 t, %1; cvt.u32.u64 %0, t; }"
        : "=r"(a) : "l"(p));
    return a;
}
__device__ __forceinline__ void mma_m16n8k16f16(float c[4], const uint32_t a[4],
                                                const uint32_t b[2]) {
    asm volatile(
        "mma.sync.aligned.m16n8k16.row.col.f32.f16.f16.f32 "
        "{%0,%1,%2,%3}, {%4,%5,%6,%7}, {%8,%9}, {%0,%1,%2,%3};"
        : "+f"(c[0]), "+f"(c[1]), "+f"(c[2]), "+f"(c[3])
        : "r"(a[0]), "r"(a[1]), "r"(a[2]), "r"(a[3]), "r"(b[0]), "r"(b[1]));
}
__device__ __forceinline__ void ldsm4(uint32_t& r0, uint32_t& r1, uint32_t& r2,
                                      uint32_t& r3, uint32_t addr) {
    asm volatile("ldmatrix.sync.aligned.m8n8.x4.shared.b16 {%0,%1,%2,%3}, [%4];"
                 : "=r"(r0), "=r"(r1), "=r"(r2), "=r"(r3) : "r"(addr));
}
__device__ __forceinline__ void cp16(uint32_t dst, const void* src) {
    asm volatile("cp.async.cg.shared.global [%0], [%1], 16;" :: "r"(dst), "l"(src));
}
#define CP_COMMIT() asm volatile("cp.async.commit_group;" ::: "memory")
#define CP_WAIT1()  asm volatile("cp.async.wait_group 1;" ::: "memory")

__device__ __forceinline__ uint32_t h2u(__half2 h) { return *(uint32_t*)&h; }

constexpr int SH    = 40;          // fp16 padded row stride (halves) = 80B
constexpr int HTILE = 128 * SH;    // halves per 128x32 fp16 tile

// ---------------------------------------------------------------------------
// 1) inv_dsq[q][k] = 1 / (d'(q,k)^2 + 1e-6)
// ---------------------------------------------------------------------------
__global__ void dist_kernel(const float* __restrict__ pos) {
    int q = blockIdx.y;
    int k = blockIdx.x * blockDim.x + threadIdx.x;
    float acc = 1e-12f;
#pragma unroll
    for (int j = 0; j < 8; j++) {
        float d = pos[q * 8 + j] - pos[k * 8 + j];
        acc = fmaf(d, d, acc);
    }
    float dist = sqrtf(acc);
    dist = dist * (1.0f + 0.15f * sinf(dist));
    dist = fmaxf(dist, 0.0f);
    float dsq = fmaf(dist, dist, 1e-6f);
    g_inv_dsq[(size_t)q * Sc + k] = 1.0f / dsq;
}

// ---------------------------------------------------------------------------
// 2) masses[bh][s] = sigmoid( x[b,s,h*128:] . mass_w[h,:] )
// ---------------------------------------------------------------------------
__global__ __launch_bounds__(256) void masses_kernel(const float* __restrict__ x,
                                                     const float* __restrict__ mw) {
    int gw   = blockIdx.x * 8 + (threadIdx.x >> 5);
    int lane = threadIdx.x & 31;
    int bh = gw / Sc;
    int s  = gw % Sc;
    int b = bh >> 3, h = bh & 7;
    const float4* xp = (const float4*)(x + ((size_t)(b * Sc + s)) * Dc + h * HDc);
    const float4* wp = (const float4*)(mw + h * HDc);
    float4 a = xp[lane];
    float4 w = wp[lane];
    float dot = a.x * w.x + a.y * w.y + a.z * w.z + a.w * w.w;
#pragma unroll
    for (int o = 16; o; o >>= 1) dot += __shfl_xor_sync(0xffffffffu, dot, o);
    if (lane == 0) g_masses[bh * Sc + s] = 1.0f / (1.0f + __expf(-dot));
}

// ---------------------------------------------------------------------------
// 3) rowmax[bh][q] = min( mq * max_k( mk[k] * inv_dsq[q][k] ), 50 )
//    One block per q row; all 16 bh at once (inv_dsq row read once).
// ---------------------------------------------------------------------------
__global__ __launch_bounds__(256) void rowmax_kernel() {
    __shared__ float red[16][257];
    int q = blockIdx.x;
    int tid = threadIdx.x;
    const float* iv = g_inv_dsq + (size_t)q * Sc;
    int k0 = tid * 8;
    float mx[16];
#pragma unroll
    for (int b = 0; b < 16; b++) mx[b] = 0.0f;   // products are > 0
#pragma unroll
    for (int j = 0; j < 2; j++) {
        float4 v = __ldg((const float4*)&iv[k0 + j * 4]);
#pragma unroll
        for (int b = 0; b < 16; b++) {
            float4 mk = __ldg((const float4*)&g_masses[b * Sc + k0 + j * 4]);
            mx[b] = fmaxf(mx[b], fmaxf(fmaxf(mk.x * v.x, mk.y * v.y),
                                       fmaxf(mk.z * v.z, mk.w * v.w)));
        }
    }
#pragma unroll
    for (int b = 0; b < 16; b++) red[b][tid] = mx[b];
    __syncthreads();
    for (int off = 128; off >= 1; off >>= 1) {
        if (tid < off) {
#pragma unroll
            for (int b = 0; b < 16; b++)
                red[b][tid] = fmaxf(red[b][tid], red[b][tid + off]);
        }
        __syncthreads();
    }
    if (tid < 16) {
        float mq = g_masses[tid * Sc + q];
        g_rowmax[tid * Sc + q] = fminf(mq * red[tid][0], 50.0f);
    }
}

// ---------------------------------------------------------------------------
// 4) f32 -> fp16 conversion pass
// ---------------------------------------------------------------------------
__global__ __launch_bounds__(256) void cvt16_kernel(const float* __restrict__ in,
                                                    __half* __restrict__ out, int n4) {
    int i = blockIdx.x * blockDim.x + threadIdx.x;
    if (i < n4) {
        float4 v = __ldg((const float4*)in + i);
        uint2 u;
        u.x = h2u(__floats2half2_rn(v.x, v.y));
        u.y = h2u(__floats2half2_rn(v.z, v.w));
        ((uint2*)out)[i] = u;
    }
}

// ---------------------------------------------------------------------------
// 5/8) fp16 GEMM (fp32 accum): C[M,N] = A[M,K] * B[N,K]^T
// ---------------------------------------------------------------------------
__global__ __launch_bounds__(256, 2) void gemm_fp16(const __half* __restrict__ A,
                                                    const __half* __restrict__ B,
                                                    float* __restrict__ C,
                                                    int N, int K) {
    extern __shared__ uint32_t sm[];
    int tid = threadIdx.x, lane = tid & 31, wid = tid >> 5;
    int wm = wid & 3, wn = wid >> 2;
    int row0 = blockIdx.y * 128, col0 = blockIdx.x * 128;
    int fr = tid >> 1;
    int fc = (tid & 1) * 16;
    uint32_t sbase = smem_u32(sm);

    int r = lane & 7, m = lane >> 3;
    int aoff[2], boff[4];
#pragma unroll
    for (int t = 0; t < 2; t++)
        aoff[t] = (wm * 32 + t * 16 + (m & 1) * 8 + r) * SH + (m >> 1) * 8;
#pragma unroll
    for (int j = 0; j < 4; j++)
        boff[j] = (wn * 64 + j * 16 + (m & 1) * 8 + r) * SH + (m >> 1) * 8;

    float c[2][8][4] = {};
    int nkt = K / 32;

    const __half* Ap = A + (size_t)(row0 + fr) * K + fc;
    const __half* Bp = B + (size_t)(col0 + fr) * K + fc;

#pragma unroll
    for (int s = 0; s < 2; s++) {
        uint32_t ast = sbase + (s * 2 * HTILE) * 2;
        uint32_t bst = ast + HTILE * 2;
        cp16(ast + (fr * SH + fc) * 2,     Ap + s * 32);
        cp16(ast + (fr * SH + fc + 8) * 2, Ap + s * 32 + 8);
        cp16(bst + (fr * SH + fc) * 2,     Bp + s * 32);
        cp16(bst + (fr * SH + fc + 8) * 2, Bp + s * 32 + 8);
        CP_COMMIT();
    }

    for (int kt = 0; kt < nkt; kt++) {
        CP_WAIT1();
        __syncthreads();
        if (kt + 2 < nkt) {
            int s = (kt + 2) % 3, k0 = (kt + 2) * 32;
            uint32_t ast = sbase + (s * 2 * HTILE) * 2;
            uint32_t bst = ast + HTILE * 2;
            cp16(ast + (fr * SH + fc) * 2,     Ap + k0);
            cp16(ast + (fr * SH + fc + 8) * 2, Ap + k0 + 8);
            cp16(bst + (fr * SH + fc) * 2,     Bp + k0);
            cp16(bst + (fr * SH + fc + 8) * 2, Bp + k0 + 8);
        }
        CP_COMMIT();
        uint32_t sa = sbase + ((kt % 3) * 2 * HTILE) * 2;
        uint32_t sb = sa + HTILE * 2;
#pragma unroll
        for (int ks = 0; ks < 2; ks++) {
            uint32_t a[2][4], bq[4][4];
#pragma unroll
            for (int t = 0; t < 2; t++)
                ldsm4(a[t][0], a[t][1], a[t][2], a[t][3], sa + (aoff[t] + ks * 16) * 2);
#pragma unroll
            for (int j = 0; j < 4; j++)
                ldsm4(bq[j][0], bq[j][1], bq[j][2], bq[j][3], sb + (boff[j] + ks * 16) * 2);
#pragma unroll
            for (int t = 0; t < 2; t++)
#pragma unroll
                for (int j = 0; j < 4; j++) {
                    uint32_t b0[2] = {bq[j][0], bq[j][2]};
                    uint32_t b1[2] = {bq[j][1], bq[j][3]};
                    mma_m16n8k16f16(c[t][2 * j],     a[t], b0);
                    mma_m16n8k16f16(c[t][2 * j + 1], a[t], b1);
                }
        }
    }

#pragma unroll
    for (int t = 0; t < 2; t++) {
        int row = row0 + wm * 32 + t * 16 + (lane >> 2);
#pragma unroll
        for (int n = 0; n < 8; n++) {
            int col = col0 + wn * 64 + n * 8 + (lane & 3) * 2;
            *(float2*)&C[(size_t)row * N + col]       = make_float2(c[t][n][0], c[t][n][1]);
            *(float2*)&C[(size_t)(row + 8) * N + col] = make_float2(c[t][n][2], c[t][n][3]);
        }
    }
}

// ---------------------------------------------------------------------------
// 6) transpose v -> g_vTh[bh][d][k]  (fp16, k contiguous)
// ---------------------------------------------------------------------------
__global__ void transpose_v() {
    __shared__ float t[32][33];
    int k0 = blockIdx.x * 32, d0 = blockIdx.y * 32, bh = blockIdx.z;
    int b = bh >> 3, h = bh & 7;
    int tx = threadIdx.x, ty = threadIdx.y;
    const float* src = g_v + (size_t)b * Sc * Dc + h * HDc;
#pragma unroll
    for (int i = 0; i < 32; i += 8)
        t[ty + i][tx] = src[(size_t)(k0 + ty + i) * Dc + d0 + tx];
    __syncthreads();
    __half* dst = g_vTh + (size_t)bh * HDc * Sc;
#pragma unroll
    for (int i = 0; i < 32; i += 8)
        dst[(size_t)(d0 + ty + i) * Sc + k0 + tx] = __float2half_rn(t[tx][ty + i]);
}

// ---------------------------------------------------------------------------
// 7) Fused attention, fp16 MMA (fp32 accum).
//    w' = exp(min(force,50) - rowmax) in (0,1] -> fp16 safe.
//    q-tile 128, k-tile 32, 256 threads. W double-buffered STS,
//    V 3-stage cp.async from g_vTh. Epilogue -> fp16 head_out.
// ---------------------------------------------------------------------------
__global__ __launch_bounds__(256, 2) void attn_fp16() {
    extern __shared__ uint32_t sm[];
    __half* Ws = (__half*)sm;                          // 2 tiles
    float* red  = (float*)((char*)sm + 5 * HTILE * 2); // after W[2]+V[3]
    float* ssum = red + 256;

    int tid = threadIdx.x, lane = tid & 31, wid = tid >> 5;
    int wm = wid & 3, wn = wid >> 2;
    int bh = blockIdx.y;
    int b = bh >> 3, h = bh & 7;
    int q0 = blockIdx.x * 128;
    int fr = tid >> 1, fc = (tid & 1) * 16;
    uint32_t sbase = smem_u32(sm);
    uint32_t vbase = sbase + 2 * HTILE * 2;

    int r = lane & 7, m = lane >> 3;
    int aoff[2], boff[4];
#pragma unroll
    for (int t = 0; t < 2; t++)
        aoff[t] = (wm * 32 + t * 16 + (m & 1) * 8 + r) * SH + (m >> 1) * 8;
#pragma unroll
    for (int j = 0; j < 4; j++)
        boff[j] = (wn * 64 + j * 16 + (m & 1) * 8 + r) * SH + (m >> 1) * 8;

    int myq = tid >> 1;
    int kh  = (tid & 1) * 16;
    const float* mrow = g_masses + bh * Sc;
    const float* drow = g_inv_dsq + (size_t)(q0 + myq) * Sc;
    const __half* vt  = g_vTh + (size_t)bh * HDc * Sc + (size_t)fr * Sc + fc;
    float mq = mrow[q0 + myq];
    float rm = g_rowmax[bh * Sc + q0 + myq];
    float lsum = 0.0f;

    float c[2][8][4] = {};
    constexpr int NKT = Sc / 32;

    // prologue: V stages 0,1 async
#pragma unroll
    for (int s = 0; s < 2; s++) {
        uint32_t vst = vbase + s * HTILE * 2;
        cp16(vst + (fr * SH + fc) * 2,     vt + s * 32);
        cp16(vst + (fr * SH + fc + 8) * 2, vt + s * 32 + 8);
        CP_COMMIT();
    }
    // scores tile 0 into W buf 0
    float4 iv[4];
#pragma unroll
    for (int j = 0; j < 4; j++) iv[j] = __ldg((const float4*)&drow[kh + j * 4]);
    {
        __half* wrow = Ws + myq * SH + kh;
        uint32_t wb[8];
#pragma unroll
        for (int j = 0; j < 4; j++) {
            float4 mk = __ldg((const float4*)&mrow[kh + j * 4]);
            float w0 = __expf(fminf(mq * mk.x * iv[j].x, 50.0f) - rm);
            float w1 = __expf(fminf(mq * mk.y * iv[j].y, 50.0f) - rm);
            float w2 = __expf(fminf(mq * mk.z * iv[j].z, 50.0f) - rm);
            float w3 = __expf(fminf(mq * mk.w * iv[j].w, 50.0f) - rm);
            lsum += (w0 + w1) + (w2 + w3);
            wb[2 * j]     = h2u(__floats2half2_rn(w0, w1));
            wb[2 * j + 1] = h2u(__floats2half2_rn(w2, w3));
        }
        *(uint4*)wrow       = make_uint4(wb[0], wb[1], wb[2], wb[3]);
        *(uint4*)(wrow + 8) = make_uint4(wb[4], wb[5], wb[6], wb[7]);
    }
#pragma unroll
    for (int j = 0; j < 4; j++) iv[j] = __ldg((const float4*)&drow[32 + kh + j * 4]);

    for (int kt = 0; kt < NKT; kt++) {
        CP_WAIT1();
        __syncthreads();
        if (kt + 2 < NKT) {
            int s = (kt + 2) % 3, k0 = (kt + 2) * 32;
            uint32_t vst = vbase + s * HTILE * 2;
            cp16(vst + (fr * SH + fc) * 2,     vt + k0);
            cp16(vst + (fr * SH + fc + 8) * 2, vt + k0 + 8);
        }
        CP_COMMIT();
        if (kt + 1 < NKT) {
            int k0n = (kt + 1) * 32;
            __half* wrow = Ws + ((kt + 1) & 1) * HTILE + myq * SH + kh;
            uint32_t wb[8];
#pragma unroll
            for (int j = 0; j < 4; j++) {
                float4 mk = __ldg((const float4*)&mrow[k0n + kh + j * 4]);
                float w0 = __expf(fminf(mq * mk.x * iv[j].x, 50.0f) - rm);
                float w1 = __expf(fminf(mq * mk.y * iv[j].y, 50.0f) - rm);
                float w2 = __expf(fminf(mq * mk.z * iv[j].z, 50.0f) - rm);
                float w3 = __expf(fminf(mq * mk.w * iv[j].w, 50.0f) - rm);
                lsum += (w0 + w1) + (w2 + w3);
                wb[2 * j]     = h2u(__floats2half2_rn(w0, w1));
                wb[2 * j + 1] = h2u(__floats2half2_rn(w2, w3));
            }
            *(uint4*)wrow       = make_uint4(wb[0], wb[1], wb[2], wb[3]);
            *(uint4*)(wrow + 8) = make_uint4(wb[4], wb[5], wb[6], wb[7]);
            if (kt + 2 < NKT) {
                int k0p = (kt + 2) * 32;
#pragma unroll
                for (int j = 0; j < 4; j++)
                    iv[j] = __ldg((const float4*)&drow[k0p + kh + j * 4]);
            }
        }
        uint32_t sa = sbase + ((kt & 1) * HTILE) * 2;
        uint32_t sb = vbase + ((kt % 3) * HTILE) * 2;
#pragma unroll
        for (int ks = 0; ks < 2; ks++) {
            uint32_t a[2][4], bq[4][4];
#pragma unroll
            for (int t = 0; t < 2; t++)
                ldsm4(a[t][0], a[t][1], a[t][2], a[t][3], sa + (aoff[t] + ks * 16) * 2);
#pragma unroll
            for (int j = 0; j < 4; j++)
                ldsm4(bq[j][0], bq[j][1], bq[j][2], bq[j][3], sb + (boff[j] + ks * 16) * 2);
#pragma unroll
            for (int t = 0; t < 2; t++)
#pragma unroll
                for (int j = 0; j < 4; j++) {
                    uint32_t b0[2] = {bq[j][0], bq[j][2]};
                    uint32_t b1[2] = {bq[j][1], bq[j][3]};
                    mma_m16n8k16f16(c[t][2 * j],     a[t], b0);
                    mma_m16n8k16f16(c[t][2 * j + 1], a[t], b1);
                }
        }
    }

    red[tid] = lsum;
    __syncthreads();
    if (tid < 128) ssum[tid] = red[2 * tid] + red[2 * tid + 1];
    __syncthreads();

#pragma unroll
    for (int t = 0; t < 2; t++) {
        int rl = wm * 32 + t * 16 + (lane >> 2);
        float r0 = 1.0f / ssum[rl];
        float r1 = 1.0f / ssum[rl + 8];
        __half* o0 = g_hoh + ((size_t)(b * Sc + q0 + rl)) * Dc + h * HDc;
        __half* o1 = g_hoh + ((size_t)(b * Sc + q0 + rl + 8)) * Dc + h * HDc;
#pragma unroll
        for (int n = 0; n < 8; n++) {
            int col = wn * 64 + n * 8 + (lane & 3) * 2;
            *(__half2*)&o0[col] = __floats2half2_rn(c[t][n][0] * r0, c[t][n][1] * r0);
            *(__half2*)&o1[col] = __floats2half2_rn(c[t][n][2] * r1, c[t][n][3] * r1);
        }
    }
}

// ---------------------------------------------------------------------------
extern "C" void kernel_launch(void* const* d_in, const int* in_sizes, int n_in,
                              void* d_out, int out_size) {
    const float* x      = (const float*)d_in[0];
    const float* mass_w = (const float*)d_in[1];
    const float* v_w    = (const float*)d_in[2];
    const float* out_w  = (const float*)d_in[3];
    const float* pos    = (const float*)d_in[4];
    float* out = (float*)d_out;

    void *pxh = nullptr, *pvwh = nullptr, *powh = nullptr, *pv = nullptr, *phoh = nullptr;
    cudaGetSymbolAddress(&pxh,  g_xh);
    cudaGetSymbolAddress(&pvwh, g_vwh);
    cudaGetSymbolAddress(&powh, g_owh);
    cudaGetSymbolAddress(&pv,   g_v);
    cudaGetSymbolAddress(&phoh, g_hoh);

    const int GEMM_SMEM = 3 * 2 * HTILE * 2;               // 61440 B
    const int ATTN_SMEM = 5 * HTILE * 2 + (256 + 128) * 4; // 52736 B
    cudaFuncSetAttribute(gemm_fp16, cudaFuncAttributeMaxDynamicSharedMemorySize, GEMM_SMEM);
    cudaFuncSetAttribute(attn_fp16, cudaFuncAttributeMaxDynamicSharedMemorySize, ATTN_SMEM);

    dist_kernel<<<dim3(Sc / 256, Sc), 256>>>(pos);
    masses_kernel<<<(Bc * Hc * Sc) / 8, 256>>>(x, mass_w);
    rowmax_kernel<<<Sc, 256>>>();
    cvt16_kernel<<<(Bc * Sc * Dc / 4 + 255) / 256, 256>>>(x, (__half*)pxh, Bc * Sc * Dc / 4);
    cvt16_kernel<<<(Dc * Dc / 4 + 255) / 256, 256>>>(v_w, (__half*)pvwh, Dc * Dc / 4);
    cvt16_kernel<<<(Dc * Dc / 4 + 255) / 256, 256>>>(out_w, (__half*)powh, Dc * Dc / 4);

    gemm_fp16<<<dim3(Dc / 128, (Bc * Sc) / 128), 256, GEMM_SMEM>>>(
        (const __half*)pxh, (const __half*)pvwh, (float*)pv, Dc, Dc);
    transpose_v<<<dim3(Sc / 32, HDc / 32, Bc * Hc), dim3(32, 8)>>>();
    attn_fp16<<<dim3(Sc / 128, Bc * Hc), 256, ATTN_SMEM>>>();
    gemm_fp16<<<dim3(Dc / 128, (Bc * Sc) / 128), 256, GEMM_SMEM>>>(
        (const __half*)phoh, (const __half*)powh, out, Dc, Dc);
}

// round 8
// speedup vs baseline: 3.4063x; 1.0297x over previous
#include <cuda_runtime.h>
#include <cuda_fp16.h>
#include <cstdint>
#include <math.h>

// Problem shape (fixed by setup_inputs)
constexpr int Bc  = 2;
constexpr int Sc  = 2048;
constexpr int Dc  = 1024;
constexpr int Hc  = 8;
constexpr int HDc = 128;

constexpr float L2E = 1.4426950408889634f;

// Scratch (no allocations allowed)
__device__ __align__(256) float    g_inv_dsq[(size_t)Sc * Sc];       // 16 MB
__device__ __align__(256) float    g_masses[Bc * Hc * Sc];           // 128 KB
__device__ __align__(256) float    g_rowmax[Bc * Hc * Sc];           // 128 KB
__device__ __align__(256) __half   g_xh[(size_t)Bc * Sc * Dc];       // 8 MB   x fp16
__device__ __align__(256) __half   g_vwh[(size_t)Dc * Dc];           // 2 MB   v_w fp16
__device__ __align__(256) __half   g_owh[(size_t)Dc * Dc];           // 2 MB   out_w fp16
__device__ __align__(256) float    g_v[(size_t)Bc * Sc * Dc];        // 32 MB
__device__ __align__(256) __half   g_vTh[(size_t)Bc * Hc * HDc * Sc];// 16 MB [bh][d][k] fp16
__device__ __align__(256) __half   g_hoh[(size_t)Bc * Sc * Dc];      // 8 MB  head_out fp16

// ---------------------------------------------------------------------------
// helpers
// ---------------------------------------------------------------------------
__device__ __forceinline__ uint32_t smem_u32(const void* p) {
    uint32_t a;
    asm("{ .reg .u64 t; cvta.to.shared.u64 t, %1; cvt.u32.u64 %0, t; }"
        : "=r"(a) : "l"(p));
    return a;
}
__device__ __forceinline__ float ex2(float x) {
    float y;
    asm("ex2.approx.f32 %0, %1;" : "=f"(y) : "f"(x));
    return y;
}
__device__ __forceinline__ float rcp_approx(float x) {
    float y;
    asm("rcp.approx.f32 %0, %1;" : "=f"(y) : "f"(x));
    return y;
}
__device__ __forceinline__ void mma_m16n8k16f16(float c[4], const uint32_t a[4],
                                                const uint32_t b[2]) {
    asm volatile(
        "mma.sync.aligned.m16n8k16.row.col.f32.f16.f16.f32 "
        "{%0,%1,%2,%3}, {%4,%5,%6,%7}, {%8,%9}, {%0,%1,%2,%3};"
        : "+f"(c[0]), "+f"(c[1]), "+f"(c[2]), "+f"(c[3])
        : "r"(a[0]), "r"(a[1]), "r"(a[2]), "r"(a[3]), "r"(b[0]), "r"(b[1]));
}
__device__ __forceinline__ void ldsm4(uint32_t& r0, uint32_t& r1, uint32_t& r2,
                                      uint32_t& r3, uint32_t addr) {
    asm volatile("ldmatrix.sync.aligned.m8n8.x4.shared.b16 {%0,%1,%2,%3}, [%4];"
                 : "=r"(r0), "=r"(r1), "=r"(r2), "=r"(r3) : "r"(addr));
}
__device__ __forceinline__ void cp16(uint32_t dst, const void* src) {
    asm volatile("cp.async.cg.shared.global [%0], [%1], 16;" :: "r"(dst), "l"(src));
}
#define CP_COMMIT() asm volatile("cp.async.commit_group;" ::: "memory")
#define CP_WAIT1()  asm volatile("cp.async.wait_group 1;" ::: "memory")

__device__ __forceinline__ uint32_t h2u(__half2 h) { return *(uint32_t*)&h; }

constexpr int SH    = 40;          // fp16 padded row stride (halves) = 80B
constexpr int HTILE = 128 * SH;    // halves per 128x32 fp16 tile

// ---------------------------------------------------------------------------
// 1) inv_dsq[q][k] = 1 / (d'(q,k)^2 + 1e-6)   (approx transcendentals)
// ---------------------------------------------------------------------------
__global__ void dist_kernel(const float* __restrict__ pos) {
    int q = blockIdx.y;
    int k = blockIdx.x * blockDim.x + threadIdx.x;
    float acc = 1e-12f;
#pragma unroll
    for (int j = 0; j < 8; j++) {
        float d = pos[q * 8 + j] - pos[k * 8 + j];
        acc = fmaf(d, d, acc);
    }
    float dist = acc * rsqrtf(acc);              // sqrt via MUFU.RSQ
    float s = __sinf(dist);
    dist = dist * fmaf(0.15f, s, 1.0f);
    dist = fmaxf(dist, 0.0f);
    float dsq = fmaf(dist, dist, 1e-6f);
    g_inv_dsq[(size_t)q * Sc + k] = rcp_approx(dsq);
}

// ---------------------------------------------------------------------------
// 2) masses[bh][s] = sigmoid( x[b,s,h*128:] . mass_w[h,:] )
// ---------------------------------------------------------------------------
__global__ __launch_bounds__(256) void masses_kernel(const float* __restrict__ x,
                                                     const float* __restrict__ mw) {
    int gw   = blockIdx.x * 8 + (threadIdx.x >> 5);
    int lane = threadIdx.x & 31;
    int bh = gw / Sc;
    int s  = gw % Sc;
    int b = bh >> 3, h = bh & 7;
    const float4* xp = (const float4*)(x + ((size_t)(b * Sc + s)) * Dc + h * HDc);
    const float4* wp = (const float4*)(mw + h * HDc);
    float4 a = xp[lane];
    float4 w = wp[lane];
    float dot = a.x * w.x + a.y * w.y + a.z * w.z + a.w * w.w;
#pragma unroll
    for (int o = 16; o; o >>= 1) dot += __shfl_xor_sync(0xffffffffu, dot, o);
    if (lane == 0) g_masses[bh * Sc + s] = 1.0f / (1.0f + __expf(-dot));
}

// ---------------------------------------------------------------------------
// 3) rowmax[bh][q] = min( mq * max_k( mk[k] * inv_dsq[q][k] ), 50 )
//    One block per q row, all 16 bh; warp-shuffle reduction.
// ---------------------------------------------------------------------------
__global__ __launch_bounds__(256) void rowmax_kernel() {
    __shared__ float sred[16][9];
    int q = blockIdx.x;
    int tid = threadIdx.x, lane = tid & 31, wrp = tid >> 5;
    const float* iv = g_inv_dsq + (size_t)q * Sc;
    int k0 = tid * 8;
    float mx[16];
#pragma unroll
    for (int b = 0; b < 16; b++) mx[b] = 0.0f;   // products are > 0
#pragma unroll
    for (int j = 0; j < 2; j++) {
        float4 v = __ldg((const float4*)&iv[k0 + j * 4]);
#pragma unroll
        for (int b = 0; b < 16; b++) {
            float4 mk = __ldg((const float4*)&g_masses[b * Sc + k0 + j * 4]);
            mx[b] = fmaxf(mx[b], fmaxf(fmaxf(mk.x * v.x, mk.y * v.y),
                                       fmaxf(mk.z * v.z, mk.w * v.w)));
        }
    }
#pragma unroll
    for (int b = 0; b < 16; b++) {
#pragma unroll
        for (int o = 16; o; o >>= 1)
            mx[b] = fmaxf(mx[b], __shfl_xor_sync(0xffffffffu, mx[b], o));
    }
    if (lane == 0)
#pragma unroll
        for (int b = 0; b < 16; b++) sred[b][wrp] = mx[b];
    __syncthreads();
    if (tid < 16) {
        float m = sred[tid][0];
#pragma unroll
        for (int i = 1; i < 8; i++) m = fmaxf(m, sred[tid][i]);
        float mq = g_masses[tid * Sc + q];
        g_rowmax[tid * Sc + q] = fminf(mq * m, 50.0f);
    }
}

// ---------------------------------------------------------------------------
// 4) f32 -> fp16 conversion pass
// ---------------------------------------------------------------------------
__global__ __launch_bounds__(256) void cvt16_kernel(const float* __restrict__ in,
                                                    __half* __restrict__ out, int n4) {
    int i = blockIdx.x * blockDim.x + threadIdx.x;
    if (i < n4) {
        float4 v = __ldg((const float4*)in + i);
        uint2 u;
        u.x = h2u(__floats2half2_rn(v.x, v.y));
        u.y = h2u(__floats2half2_rn(v.z, v.w));
        ((uint2*)out)[i] = u;
    }
}

// ---------------------------------------------------------------------------
// 5/8) fp16 GEMM (fp32 accum): C[M,N] = A[M,K] * B[N,K]^T
// ---------------------------------------------------------------------------
__global__ __launch_bounds__(256, 2) void gemm_fp16(const __half* __restrict__ A,
                                                    const __half* __restrict__ B,
                                                    float* __restrict__ C,
                                                    int N, int K) {
    extern __shared__ uint32_t sm[];
    int tid = threadIdx.x, lane = tid & 31, wid = tid >> 5;
    int wm = wid & 3, wn = wid >> 2;
    int row0 = blockIdx.y * 128, col0 = blockIdx.x * 128;
    int fr = tid >> 1;
    int fc = (tid & 1) * 16;
    uint32_t sbase = smem_u32(sm);

    int r = lane & 7, m = lane >> 3;
    int aoff[2], boff[4];
#pragma unroll
    for (int t = 0; t < 2; t++)
        aoff[t] = (wm * 32 + t * 16 + (m & 1) * 8 + r) * SH + (m >> 1) * 8;
#pragma unroll
    for (int j = 0; j < 4; j++)
        boff[j] = (wn * 64 + j * 16 + (m & 1) * 8 + r) * SH + (m >> 1) * 8;

    float c[2][8][4] = {};
    int nkt = K / 32;

    const __half* Ap = A + (size_t)(row0 + fr) * K + fc;
    const __half* Bp = B + (size_t)(col0 + fr) * K + fc;

#pragma unroll
    for (int s = 0; s < 2; s++) {
        uint32_t ast = sbase + (s * 2 * HTILE) * 2;
        uint32_t bst = ast + HTILE * 2;
        cp16(ast + (fr * SH + fc) * 2,     Ap + s * 32);
        cp16(ast + (fr * SH + fc + 8) * 2, Ap + s * 32 + 8);
        cp16(bst + (fr * SH + fc) * 2,     Bp + s * 32);
        cp16(bst + (fr * SH + fc + 8) * 2, Bp + s * 32 + 8);
        CP_COMMIT();
    }

    for (int kt = 0; kt < nkt; kt++) {
        CP_WAIT1();
        __syncthreads();
        if (kt + 2 < nkt) {
            int s = (kt + 2) % 3, k0 = (kt + 2) * 32;
            uint32_t ast = sbase + (s * 2 * HTILE) * 2;
            uint32_t bst = ast + HTILE * 2;
            cp16(ast + (fr * SH + fc) * 2,     Ap + k0);
            cp16(ast + (fr * SH + fc + 8) * 2, Ap + k0 + 8);
            cp16(bst + (fr * SH + fc) * 2,     Bp + k0);
            cp16(bst + (fr * SH + fc + 8) * 2, Bp + k0 + 8);
        }
        CP_COMMIT();
        uint32_t sa = sbase + ((kt % 3) * 2 * HTILE) * 2;
        uint32_t sb = sa + HTILE * 2;
#pragma unroll
        for (int ks = 0; ks < 2; ks++) {
            uint32_t a[2][4], bq[4][4];
#pragma unroll
            for (int t = 0; t < 2; t++)
                ldsm4(a[t][0], a[t][1], a[t][2], a[t][3], sa + (aoff[t] + ks * 16) * 2);
#pragma unroll
            for (int j = 0; j < 4; j++)
                ldsm4(bq[j][0], bq[j][1], bq[j][2], bq[j][3], sb + (boff[j] + ks * 16) * 2);
#pragma unroll
            for (int t = 0; t < 2; t++)
#pragma unroll
                for (int j = 0; j < 4; j++) {
                    uint32_t b0[2] = {bq[j][0], bq[j][2]};
                    uint32_t b1[2] = {bq[j][1], bq[j][3]};
                    mma_m16n8k16f16(c[t][2 * j],     a[t], b0);
                    mma_m16n8k16f16(c[t][2 * j + 1], a[t], b1);
                }
        }
    }

#pragma unroll
    for (int t = 0; t < 2; t++) {
        int row = row0 + wm * 32 + t * 16 + (lane >> 2);
#pragma unroll
        for (int n = 0; n < 8; n++) {
            int col = col0 + wn * 64 + n * 8 + (lane & 3) * 2;
            *(float2*)&C[(size_t)row * N + col]       = make_float2(c[t][n][0], c[t][n][1]);
            *(float2*)&C[(size_t)(row + 8) * N + col] = make_float2(c[t][n][2], c[t][n][3]);
        }
    }
}

// ---------------------------------------------------------------------------
// 6) transpose v -> g_vTh[bh][d][k]  (fp16, k contiguous)
// ---------------------------------------------------------------------------
__global__ void transpose_v() {
    __shared__ float t[32][33];
    int k0 = blockIdx.x * 32, d0 = blockIdx.y * 32, bh = blockIdx.z;
    int b = bh >> 3, h = bh & 7;
    int tx = threadIdx.x, ty = threadIdx.y;
    const float* src = g_v + (size_t)b * Sc * Dc + h * HDc;
#pragma unroll
    for (int i = 0; i < 32; i += 8)
        t[ty + i][tx] = src[(size_t)(k0 + ty + i) * Dc + d0 + tx];
    __syncthreads();
    __half* dst = g_vTh + (size_t)bh * HDc * Sc;
#pragma unroll
    for (int i = 0; i < 32; i += 8)
        dst[(size_t)(d0 + ty + i) * Sc + k0 + tx] = __float2half_rn(t[tx][ty + i]);
}

// ---------------------------------------------------------------------------
// score emit: 4 weights -> 2 packed fp16x2
//   arg = min( (mk*iv)*a + nb , cap ),  w = 2^arg
//   a = mq*L2E, nb = -rm*L2E, cap = (50-rm)*L2E
// ---------------------------------------------------------------------------
__device__ __forceinline__ void emit4(float4 mk, float4 iv, float a, float nb,
                                      float cap, uint32_t& lo, uint32_t& hi) {
    float w0 = ex2(fminf(fmaf(mk.x * iv.x, a, nb), cap));
    float w1 = ex2(fminf(fmaf(mk.y * iv.y, a, nb), cap));
    float w2 = ex2(fminf(fmaf(mk.z * iv.z, a, nb), cap));
    float w3 = ex2(fminf(fmaf(mk.w * iv.w, a, nb), cap));
    lo = h2u(__floats2half2_rn(w0, w1));
    hi = h2u(__floats2half2_rn(w2, w3));
}

// ---------------------------------------------------------------------------
// 7) Fused attention, fp16 MMA (fp32 accum). Row sums via ones-column MMA
//    (denominator uses the SAME rounded fp16 weights as the numerator).
// ---------------------------------------------------------------------------
__global__ __launch_bounds__(256, 2) void attn_fp16() {
    extern __shared__ uint32_t sm[];
    __half* Ws = (__half*)sm;                          // 2 W tiles then 3 V tiles

    int tid = threadIdx.x, lane = tid & 31, wid = tid >> 5;
    int wm = wid & 3, wn = wid >> 2;
    int bh = blockIdx.y;
    int b = bh >> 3, h = bh & 7;
    int q0 = blockIdx.x * 128;
    int fr = tid >> 1, fc = (tid & 1) * 16;
    uint32_t sbase = smem_u32(sm);
    uint32_t vbase = sbase + 2 * HTILE * 2;

    int r = lane & 7, m = lane >> 3;
    int aoff[2], boff[4];
#pragma unroll
    for (int t = 0; t < 2; t++)
        aoff[t] = (wm * 32 + t * 16 + (m & 1) * 8 + r) * SH + (m >> 1) * 8;
#pragma unroll
    for (int j = 0; j < 4; j++)
        boff[j] = (wn * 64 + j * 16 + (m & 1) * 8 + r) * SH + (m >> 1) * 8;

    int myq = tid >> 1;
    int kh  = (tid & 1) * 16;
    const float* mrow = g_masses + bh * Sc;
    const float* drow = g_inv_dsq + (size_t)(q0 + myq) * Sc;
    const __half* vt  = g_vTh + (size_t)bh * HDc * Sc + (size_t)fr * Sc + fc;
    float mq = mrow[q0 + myq];
    float rm = g_rowmax[bh * Sc + q0 + myq];
    float sa_mul = mq * L2E;
    float nb = -rm * L2E;
    float cap = (50.0f - rm) * L2E;

    float c[2][8][4] = {};
    float csum[2][4] = {};
    const uint32_t bones[2] = {0x3C003C00u, 0x3C003C00u};  // half2(1,1) x2
    constexpr int NKT = Sc / 32;

    // prologue: V stages 0,1 async
#pragma unroll
    for (int s = 0; s < 2; s++) {
        uint32_t vst = vbase + s * HTILE * 2;
        cp16(vst + (fr * SH + fc) * 2,     vt + s * 32);
        cp16(vst + (fr * SH + fc + 8) * 2, vt + s * 32 + 8);
        CP_COMMIT();
    }
    // scores tile 0 into W buf 0
    float4 iv[4];
#pragma unroll
    for (int j = 0; j < 4; j++) iv[j] = __ldg((const float4*)&drow[kh + j * 4]);
    {
        __half* wrow = Ws + myq * SH + kh;
        uint32_t wb[8];
#pragma unroll
        for (int j = 0; j < 4; j++) {
            float4 mk = __ldg((const float4*)&mrow[kh + j * 4]);
            emit4(mk, iv[j], sa_mul, nb, cap, wb[2 * j], wb[2 * j + 1]);
        }
        *(uint4*)wrow       = make_uint4(wb[0], wb[1], wb[2], wb[3]);
        *(uint4*)(wrow + 8) = make_uint4(wb[4], wb[5], wb[6], wb[7]);
    }
#pragma unroll
    for (int j = 0; j < 4; j++) iv[j] = __ldg((const float4*)&drow[32 + kh + j * 4]);

    for (int kt = 0; kt < NKT; kt++) {
        CP_WAIT1();
        __syncthreads();
        if (kt + 2 < NKT) {
            int s = (kt + 2) % 3, k0 = (kt + 2) * 32;
            uint32_t vst = vbase + s * HTILE * 2;
            cp16(vst + (fr * SH + fc) * 2,     vt + k0);
            cp16(vst + (fr * SH + fc + 8) * 2, vt + k0 + 8);
        }
        CP_COMMIT();
        if (kt + 1 < NKT) {
            int k0n = (kt + 1) * 32;
            __half* wrow = Ws + ((kt + 1) & 1) * HTILE + myq * SH + kh;
            uint32_t wb[8];
#pragma unroll
            for (int j = 0; j < 4; j++) {
                float4 mk = __ldg((const float4*)&mrow[k0n + kh + j * 4]);
                emit4(mk, iv[j], sa_mul, nb, cap, wb[2 * j], wb[2 * j + 1]);
            }
            *(uint4*)wrow       = make_uint4(wb[0], wb[1], wb[2], wb[3]);
            *(uint4*)(wrow + 8) = make_uint4(wb[4], wb[5], wb[6], wb[7]);
            if (kt + 2 < NKT) {
                int k0p = (kt + 2) * 32;
#pragma unroll
                for (int j = 0; j < 4; j++)
                    iv[j] = __ldg((const float4*)&drow[k0p + kh + j * 4]);
            }
        }
        uint32_t sa = sbase + ((kt & 1) * HTILE) * 2;
        uint32_t sb = vbase + ((kt % 3) * HTILE) * 2;
#pragma unroll
        for (int ks = 0; ks < 2; ks++) {
            uint32_t a[2][4], bq[4][4];
#pragma unroll
            for (int t = 0; t < 2; t++)
                ldsm4(a[t][0], a[t][1], a[t][2], a[t][3], sa + (aoff[t] + ks * 16) * 2);
#pragma unroll
            for (int j = 0; j < 4; j++)
                ldsm4(bq[j][0], bq[j][1], bq[j][2], bq[j][3], sb + (boff[j] + ks * 16) * 2);
#pragma unroll
            for (int t = 0; t < 2; t++) {
#pragma unroll
                for (int j = 0; j < 4; j++) {
                    uint32_t b0[2] = {bq[j][0], bq[j][2]};
                    uint32_t b1[2] = {bq[j][1], bq[j][3]};
                    mma_m16n8k16f16(c[t][2 * j],     a[t], b0);
                    mma_m16n8k16f16(c[t][2 * j + 1], a[t], b1);
                }
                mma_m16n8k16f16(csum[t], a[t], bones);   // row sums
            }
        }
    }

    // epilogue: every column of csum[t] equals the row sum
#pragma unroll
    for (int t = 0; t < 2; t++) {
        int rl = wm * 32 + t * 16 + (lane >> 2);
        float r0 = 1.0f / csum[t][0];
        float r1 = 1.0f / csum[t][2];
        __half* o0 = g_hoh + ((size_t)(b * Sc + q0 + rl)) * Dc + h * HDc;
        __half* o1 = g_hoh + ((size_t)(b * Sc + q0 + rl + 8)) * Dc + h * HDc;
#pragma unroll
        for (int n = 0; n < 8; n++) {
            int col = wn * 64 + n * 8 + (lane & 3) * 2;
            *(__half2*)&o0[col] = __floats2half2_rn(c[t][n][0] * r0, c[t][n][1] * r0);
            *(__half2*)&o1[col] = __floats2half2_rn(c[t][n][2] * r1, c[t][n][3] * r1);
        }
    }
}

// ---------------------------------------------------------------------------
extern "C" void kernel_launch(void* const* d_in, const int* in_sizes, int n_in,
                              void* d_out, int out_size) {
    const float* x      = (const float*)d_in[0];
    const float* mass_w = (const float*)d_in[1];
    const float* v_w    = (const float*)d_in[2];
    const float* out_w  = (const float*)d_in[3];
    const float* pos    = (const float*)d_in[4];
    float* out = (float*)d_out;

    void *pxh = nullptr, *pvwh = nullptr, *powh = nullptr, *pv = nullptr, *phoh = nullptr;
    cudaGetSymbolAddress(&pxh,  g_xh);
    cudaGetSymbolAddress(&pvwh, g_vwh);
    cudaGetSymbolAddress(&powh, g_owh);
    cudaGetSymbolAddress(&pv,   g_v);
    cudaGetSymbolAddress(&phoh, g_hoh);

    const int GEMM_SMEM = 3 * 2 * HTILE * 2;   // 61440 B
    const int ATTN_SMEM = 5 * HTILE * 2;       // 51200 B
    cudaFuncSetAttribute(gemm_fp16, cudaFuncAttributeMaxDynamicSharedMemorySize, GEMM_SMEM);
    cudaFuncSetAttribute(attn_fp16, cudaFuncAttributeMaxDynamicSharedMemorySize, ATTN_SMEM);

    dist_kernel<<<dim3(Sc / 256, Sc), 256>>>(pos);
    masses_kernel<<<(Bc * Hc * Sc) / 8, 256>>>(x, mass_w);
    rowmax_kernel<<<Sc, 256>>>();
    cvt16_kernel<<<(Bc * Sc * Dc / 4 + 255) / 256, 256>>>(x, (__half*)pxh, Bc * Sc * Dc / 4);
    cvt16_kernel<<<(Dc * Dc / 4 + 255) / 256, 256>>>(v_w, (__half*)pvwh, Dc * Dc / 4);
    cvt16_kernel<<<(Dc * Dc / 4 + 255) / 256, 256>>>(out_w, (__half*)powh, Dc * Dc / 4);

    gemm_fp16<<<dim3(Dc / 128, (Bc * Sc) / 128), 256, GEMM_SMEM>>>(
        (const __half*)pxh, (const __half*)pvwh, (float*)pv, Dc, Dc);
    transpose_v<<<dim3(Sc / 32, HDc / 32, Bc * Hc), dim3(32, 8)>>>();
    attn_fp16<<<dim3(Sc / 128, Bc * Hc), 256, ATTN_SMEM>>>();
    gemm_fp16<<<dim3(Dc / 128, (Bc * Sc) / 128), 256, GEMM_SMEM>>>(
        (const __half*)phoh, (const __half*)powh, out, Dc, Dc);
}